// round 13
// baseline (speedup 1.0000x reference)
#include <cuda_runtime.h>
#include <cuda_fp16.h>
#include <math.h>
#include <stdint.h>

#define NV 20000
#define NF 40000
#define EE 320000
#define GG 64
#define D  256
#define D2 512

// ---------------- scratch (device globals; no allocation allowed) ----------
__device__ __half g_hFa[NF * D], g_hFb[NF * D], g_hFh[NF * D], g_hFagg[NF * D];
__device__ __half g_hVa[NV * D], g_hVb[NV * D], g_hVh[NV * D], g_hVagg[NV * D];
__device__ __half g_hW[1048576];
__device__ float g_gate[NF];
__device__ float g_Z[GG * D];
__device__ int   g_part[512];
// CSR scratch
__device__ int g_cntF[NF], g_cntV[NV];
__device__ int g_offF[NF + 1], g_offV[NV + 1];
__device__ int g_curF[NF], g_curV[NV];
__device__ int g_elF[EE], g_elV[EE];

enum { EP_NONE = 0, EP_BIAS = 1, EP_RELU_BIAS = 2, EP_RELU_BIAS_RES = 3 };

__device__ __forceinline__ uint32_t smem_u32(const void* p) {
    uint32_t a;
    asm("{ .reg .u64 t; cvta.to.shared.u64 t, %1; cvt.u32.u64 %0, t; }"
        : "=r"(a) : "l"(p));
    return a;
}
__device__ __forceinline__ void ldm_x4(unsigned& r0, unsigned& r1,
                                       unsigned& r2, unsigned& r3, uint32_t a) {
    asm volatile("ldmatrix.sync.aligned.m8n8.x4.shared.b16 {%0,%1,%2,%3}, [%4];"
                 : "=r"(r0), "=r"(r1), "=r"(r2), "=r"(r3) : "r"(a));
}
__device__ __forceinline__ void ldm_x4_t(unsigned& r0, unsigned& r1,
                                         unsigned& r2, unsigned& r3, uint32_t a) {
    asm volatile("ldmatrix.sync.aligned.m8n8.x4.trans.shared.b16 {%0,%1,%2,%3}, [%4];"
                 : "=r"(r0), "=r"(r1), "=r"(r2), "=r"(r3) : "r"(a));
}
__device__ __forceinline__ void mma_f16(float* d, const unsigned* a,
                                        const unsigned* b, const float* c) {
    asm volatile(
        "mma.sync.aligned.m16n8k16.row.col.f32.f16.f16.f32 "
        "{%0,%1,%2,%3}, {%4,%5,%6,%7}, {%8,%9}, {%10,%11,%12,%13};"
        : "=f"(d[0]), "=f"(d[1]), "=f"(d[2]), "=f"(d[3])
        : "r"(a[0]), "r"(a[1]), "r"(a[2]), "r"(a[3]),
          "r"(b[0]), "r"(b[1]),
          "f"(c[0]), "f"(c[1]), "f"(c[2]), "f"(c[3]));
}

#define ASH 5120
#define BSH 4352
#define BS_BASE 40960
#define SMEM_BYTES 75776

// ---- GEMM body: C[128x128 tile] = concat-A[M x KTOT] @ W[KTOT x 256] ------
// fp16 in, fp32 accumulate, half out; optional fp32 secondary output.
template <int MODE, int KTOT, bool F32OUT>
__device__ __forceinline__ void gemm_body(
    char* smem,
    const __half* __restrict__ A0, const __half* __restrict__ A1,
    const __half* __restrict__ W, __half* __restrict__ Cout,
    const float* __restrict__ bias, const __half* __restrict__ res,
    float* __restrict__ Cout32,
    int M, int yBlk, int xBlk)
{
    __half* AsB = reinterpret_cast<__half*>(smem);
    __half* BsB = reinterpret_cast<__half*>(smem + BS_BASE);

    const int tid  = threadIdx.x;
    const int wid  = tid >> 5;
    const int lane = tid & 31;
    const int g = lane >> 2;
    const int c = lane & 3;
    const int rowBase = yBlk * 128;
    const int colBase = xBlk * 128;
    const int wr = (wid & 1) * 64;
    const int wc = (wid >> 1) * 32;

    float acc[4][4][4];
#pragma unroll
    for (int i = 0; i < 4; i++)
#pragma unroll
        for (int j = 0; j < 4; j++)
#pragma unroll
            for (int k = 0; k < 4; k++) acc[i][j][k] = 0.f;

    auto issue = [&](int slab) {
        const __half* Asrc = (KTOT == 512 && slab >= 8) ? A1 : A0;
        const int kb = (slab * 32) & 255;
        __half* As = AsB + (slab & 3) * ASH;
        __half* Bs = BsB + (slab & 3) * BSH;
#pragma unroll
        for (int it = 0; it < 2; it++) {
            const int id = it * 256 + tid;
            const int r = id >> 2, kq = id & 3;
            const int gr = rowBase + r;
            const int grc = (gr < M) ? gr : (M - 1);
            const __half* src = &Asrc[(size_t)grc * D + kb + kq * 8];
            const uint32_t dst = smem_u32(As + r * 40 + kq * 8);
            const int sz = (gr < M) ? 16 : 0;
            asm volatile("cp.async.cg.shared.global [%0], [%1], 16, %2;\n"
                         :: "r"(dst), "l"(src), "r"(sz) : "memory");
        }
#pragma unroll
        for (int it = 0; it < 2; it++) {
            const int id = it * 256 + tid;
            const int kk = id >> 4, n8 = (id & 15) * 8;
            const __half* src = &W[(size_t)(slab * 32 + kk) * D + colBase + n8];
            const uint32_t dst = smem_u32(Bs + kk * 136 + n8);
            asm volatile("cp.async.cg.shared.global [%0], [%1], 16;\n"
                         :: "r"(dst), "l"(src) : "memory");
        }
        asm volatile("cp.async.commit_group;\n" ::: "memory");
    };

    constexpr int NSLAB = KTOT / 32;
    issue(0); issue(1); issue(2);

    for (int s = 0; s < NSLAB; s++) {
        asm volatile("cp.async.wait_group 2;\n" ::: "memory");
        __syncthreads();
        if (s + 3 < NSLAB) issue(s + 3);

        const uint32_t aBase = smem_u32(AsB + (s & 3) * ASH);
        const uint32_t bBase = smem_u32(BsB + (s & 3) * BSH);
#pragma unroll
        for (int ks = 0; ks < 32; ks += 16) {
            unsigned a[4][4], b[4][2];
#pragma unroll
            for (int mf = 0; mf < 4; mf++) {
                const uint32_t addr = aBase +
                    (((wr + mf * 16 + (lane & 15)) * 40 + ks + (lane >> 4) * 8) << 1);
                ldm_x4(a[mf][0], a[mf][1], a[mf][2], a[mf][3], addr);
            }
#pragma unroll
            for (int p = 0; p < 2; p++) {
                const uint32_t addr = bBase +
                    ((((ks + (lane & 7) + ((lane >> 3) & 1) * 8)) * 136 +
                      wc + p * 16 + (lane >> 4) * 8) << 1);
                ldm_x4_t(b[2 * p][0], b[2 * p][1], b[2 * p + 1][0], b[2 * p + 1][1], addr);
            }
#pragma unroll
            for (int mf = 0; mf < 4; mf++)
#pragma unroll
                for (int nf = 0; nf < 4; nf++)
                    mma_f16(acc[mf][nf], a[mf], b[nf], acc[mf][nf]);
        }
    }

#pragma unroll
    for (int mf = 0; mf < 4; mf++) {
#pragma unroll
        for (int half = 0; half < 2; half++) {
            const int r = rowBase + wr + mf * 16 + g + half * 8;
            if (r >= M) continue;
#pragma unroll
            for (int nf = 0; nf < 4; nf++) {
                const int col = colBase + wc + nf * 8 + 2 * c;
                float2 v = make_float2(acc[mf][nf][half * 2], acc[mf][nf][half * 2 + 1]);
                if (MODE == EP_BIAS) {
                    v.x += bias[col + 0];
                    v.y += bias[col + 1];
                } else if (MODE == EP_RELU_BIAS || MODE == EP_RELU_BIAS_RES) {
                    v.x = fmaxf(v.x + bias[col + 0], 0.f);
                    v.y = fmaxf(v.y + bias[col + 1], 0.f);
                    if (MODE == EP_RELU_BIAS_RES) {
                        const __half2 rr = *reinterpret_cast<const __half2*>(&res[(size_t)r * D + col]);
                        const float2 rf = __half22float2(rr);
                        v.x += rf.x; v.y += rf.y;
                    }
                }
                *reinterpret_cast<__half2*>(&Cout[(size_t)r * D + col]) =
                    __floats2half2_rn(v.x, v.y);
                if (F32OUT) {
                    const float2 hf = __half22float2(__floats2half2_rn(v.x, v.y));
                    *reinterpret_cast<float2*>(&Cout32[(size_t)r * D + col]) = hf;
                }
            }
        }
    }
}

template <int MODE, int KTOT, bool F32OUT>
__global__ __launch_bounds__(256, 2)
void gemm_single(const __half* __restrict__ A0, const __half* __restrict__ A1,
                 const __half* __restrict__ W, __half* __restrict__ Cout,
                 const float* __restrict__ bias, const __half* __restrict__ res,
                 float* __restrict__ Cout32, int M)
{
    extern __shared__ char smem[];
    gemm_body<MODE, KTOT, F32OUT>(smem, A0, A1, W, Cout, bias, res, Cout32, M,
                                  blockIdx.y, blockIdx.x);
}

template <int MODEA, int MODEB>
__global__ __launch_bounds__(256, 2)
void gemm_dual(const __half* __restrict__ Aa, const __half* __restrict__ Wa,
               __half* __restrict__ Ca, const float* __restrict__ biasa,
               int Ma, int nYa,
               const __half* __restrict__ Ab, const __half* __restrict__ Wb,
               __half* __restrict__ Cb, int Mb)
{
    extern __shared__ char smem[];
    if ((int)blockIdx.y < nYa)
        gemm_body<MODEA, 256, false>(smem, Aa, nullptr, Wa, Ca, biasa, nullptr,
                                     nullptr, Ma, blockIdx.y, blockIdx.x);
    else
        gemm_body<MODEB, 256, false>(smem, Ab, nullptr, Wb, Cb, nullptr, nullptr,
                                     nullptr, Mb, blockIdx.y - nYa, blockIdx.x);
}

// ---------------- batched fp32 -> fp16 convert -------------------------------
struct CvtArgs {
    const float* src[6];
    __half* dst[6];
    int off[7];
};
__global__ __launch_bounds__(256)
void convert_multi(CvtArgs a)
{
    const int i = blockIdx.x * 256 + threadIdx.x;
    if (i >= a.off[6]) return;
    int s = 0;
    while (i >= a.off[s + 1]) s++;
    const int j = i - a.off[s];
    a.dst[s][j] = __float2half_rn(__ldg(&a.src[s][j]));
}

// ---------------- CSR build --------------------------------------------------
__global__ __launch_bounds__(256)
void hist_kernel(const int* __restrict__ src, const int* __restrict__ dst,
                 int* cntF, int* cntV)
{
    const int e = blockIdx.x * 256 + threadIdx.x;
    if (e >= EE) return;
    atomicAdd(&cntF[__ldg(&dst[e])], 1);
    atomicAdd(&cntV[__ldg(&src[e])], 1);
}

// fused F+V hierarchical scan
__global__ __launch_bounds__(256)
void blk_sum2(const int* __restrict__ cntF, int nF, const int* __restrict__ cntV,
              int nV, int nbF, int* __restrict__ part)
{
    const bool isV = (int)blockIdx.x >= nbF;
    const int b = isV ? (blockIdx.x - nbF) : blockIdx.x;
    const int* cnt = isV ? cntV : cntF;
    const int n = isV ? nV : nF;
    const int i = b * 256 + threadIdx.x;
    int x = (i < n) ? cnt[i] : 0;
#pragma unroll
    for (int o = 16; o > 0; o >>= 1) x += __shfl_xor_sync(0xffffffffu, x, o);
    __shared__ int ws[8];
    if ((threadIdx.x & 31) == 0) ws[threadIdx.x >> 5] = x;
    __syncthreads();
    if (threadIdx.x == 0) {
        int t = 0;
#pragma unroll
        for (int q = 0; q < 8; q++) t += ws[q];
        part[(isV ? 256 : 0) + b] = t;
    }
}

__global__ __launch_bounds__(256)
void scan_part2(int* __restrict__ part, int nbF, int nbV,
                int* __restrict__ totF, int* __restrict__ totV)
{
    const bool isV = blockIdx.x == 1;
    int* p = part + (isV ? 256 : 0);
    const int nb = isV ? nbV : nbF;
    int* total_out = isV ? totV : totF;
    const int t = threadIdx.x, lane = t & 31, w = t >> 5;
    const int x = (t < nb) ? p[t] : 0;
    int incl = x;
#pragma unroll
    for (int o = 1; o < 32; o <<= 1) {
        const int v = __shfl_up_sync(0xffffffffu, incl, o);
        if (lane >= o) incl += v;
    }
    __shared__ int ws[8], wex[8];
    if (lane == 31) ws[w] = incl;
    __syncthreads();
    if (t == 0) {
        int s = 0;
#pragma unroll
        for (int q = 0; q < 8; q++) { wex[q] = s; s += ws[q]; }
        total_out[0] = s;
    }
    __syncthreads();
    if (t < nb) p[t] = wex[w] + incl - x;
}

__global__ __launch_bounds__(256)
void scan_apply2(const int* __restrict__ cntF, int nF,
                 const int* __restrict__ cntV, int nV, int nbF,
                 const int* __restrict__ part,
                 int* __restrict__ offF, int* __restrict__ curF,
                 int* __restrict__ offV, int* __restrict__ curV)
{
    const bool isV = (int)blockIdx.x >= nbF;
    const int b = isV ? (blockIdx.x - nbF) : blockIdx.x;
    const int* cnt = isV ? cntV : cntF;
    const int n = isV ? nV : nF;
    int* off = isV ? offV : offF;
    int* cur = isV ? curV : curF;
    const int base = isV ? 256 : 0;
    const int i = b * 256 + threadIdx.x;
    const int t = threadIdx.x, lane = t & 31, w = t >> 5;
    const int x = (i < n) ? cnt[i] : 0;
    int incl = x;
#pragma unroll
    for (int o = 1; o < 32; o <<= 1) {
        const int v = __shfl_up_sync(0xffffffffu, incl, o);
        if (lane >= o) incl += v;
    }
    __shared__ int ws[8], wex[8];
    if (lane == 31) ws[w] = incl;
    __syncthreads();
    if (t == 0) {
        int s = 0;
#pragma unroll
        for (int q = 0; q < 8; q++) { wex[q] = s; s += ws[q]; }
    }
    __syncthreads();
    const int ex = part[base + b] + wex[w] + incl - x;
    if (i < n) { off[i] = ex; cur[i] = ex; }
}

__global__ __launch_bounds__(256)
void scatter_kernel(const int* __restrict__ src, const int* __restrict__ dst,
                    int* curF, int* curV, int* elF, int* elV)
{
    const int e = blockIdx.x * 256 + threadIdx.x;
    if (e >= EE) return;
    const int s = __ldg(&src[e]);
    const int d2 = __ldg(&dst[e]);
    elF[atomicAdd(&curF[d2], 1)] = s;
    elV[atomicAdd(&curV[s], 1)] = d2;
}

// ---------------- CSR gather-aggregate (half in, half out) -------------------
__global__ __launch_bounds__(256)
void aggregate(const __half* __restrict__ Hself, const __half* __restrict__ Hother,
               const int* __restrict__ off, const int* __restrict__ elist,
               __half* __restrict__ out, int n)
{
    const int row = blockIdx.x * 8 + threadIdx.y;
    if (row >= n) return;
    const int d = threadIdx.x * 8;
    const __half2* sp = reinterpret_cast<const __half2*>(&Hself[(size_t)row * D + d]);
    float2 s0 = __half22float2(sp[0]), s1 = __half22float2(sp[1]);
    float2 s2 = __half22float2(sp[2]), s3 = __half22float2(sp[3]);
    float a0x = 0.f, a0y = 0.f, a1x = 0.f, a1y = 0.f;
    float a2x = 0.f, a2y = 0.f, a3x = 0.f, a3y = 0.f;
    int j = __ldg(&off[row]);
    const int e = __ldg(&off[row + 1]);
    for (; j < e; j++) {
        const int o = __ldg(&elist[j]);
        const __half2* op = reinterpret_cast<const __half2*>(&Hother[(size_t)o * D + d]);
        const float2 v0 = __half22float2(op[0]), v1 = __half22float2(op[1]);
        const float2 v2 = __half22float2(op[2]), v3 = __half22float2(op[3]);
        a0x += fmaxf(s0.x + v0.x, 0.f); a0y += fmaxf(s0.y + v0.y, 0.f);
        a1x += fmaxf(s1.x + v1.x, 0.f); a1y += fmaxf(s1.y + v1.y, 0.f);
        a2x += fmaxf(s2.x + v2.x, 0.f); a2y += fmaxf(s2.y + v2.y, 0.f);
        a3x += fmaxf(s3.x + v3.x, 0.f); a3y += fmaxf(s3.y + v3.y, 0.f);
    }
    __half2* op2 = reinterpret_cast<__half2*>(&out[(size_t)row * D + d]);
    op2[0] = __floats2half2_rn(a0x, a0y);
    op2[1] = __floats2half2_rn(a1x, a1y);
    op2[2] = __floats2half2_rn(a2x, a2y);
    op2[3] = __floats2half2_rn(a3x, a3y);
}

// ---------------- attention pooling -----------------------------------------
__global__ __launch_bounds__(256)
void gate_kernel(const __half* __restrict__ F, const float* __restrict__ gW,
                 const float* __restrict__ gb, float* __restrict__ gate)
{
    const int w = threadIdx.x >> 5, lane = threadIdx.x & 31;
    const int row = blockIdx.x * 8 + w;
    if (row >= NF) return;
    float s = 0.f;
#pragma unroll
    for (int i = 0; i < 8; i++) {
        const int k = lane + i * 32;
        s += __half2float(F[(size_t)row * D + k]) * __ldg(&gW[k]);
    }
#pragma unroll
    for (int o = 16; o > 0; o >>= 1) s += __shfl_xor_sync(0xffffffff, s, o);
    if (lane == 0) gate[row] = s + gb[0];
}

__device__ __forceinline__ int lbound(const int* __restrict__ a, int n, int v)
{
    int lo = 0, hi = n;
    while (lo < hi) {
        const int mid = (lo + hi) >> 1;
        if (a[mid] < v) lo = mid + 1; else hi = mid;
    }
    return lo;
}

// Z[g] = sum_i alpha_i * F2[i]  (weighted mean of factor rows; affine pooling
// identity lets us defer @attW to the tiny G x D stage.)
__global__ __launch_bounds__(256)
void graph_agg(const float* __restrict__ gate, const __half* __restrict__ F,
               const int* __restrict__ batch, float* __restrict__ Z)
{
    __shared__ float red[256];
    __shared__ int sse[2];
    const int g = blockIdx.x, tid = threadIdx.x;
    if (tid == 0) sse[0] = lbound(batch, NF, g);
    if (tid == 1) sse[1] = lbound(batch, NF, g + 1);
    __syncthreads();
    const int s = sse[0], e = sse[1];

    float m = -INFINITY;
    for (int i = s + tid; i < e; i += 256) m = fmaxf(m, __ldg(&gate[i]));
    red[tid] = m; __syncthreads();
    for (int o = 128; o > 0; o >>= 1) {
        if (tid < o) red[tid] = fmaxf(red[tid], red[tid + o]);
        __syncthreads();
    }
    const float mm = red[0]; __syncthreads();

    float sum = 0.f;
    for (int i = s + tid; i < e; i += 256) sum += expf(__ldg(&gate[i]) - mm);
    red[tid] = sum; __syncthreads();
    for (int o = 128; o > 0; o >>= 1) {
        if (tid < o) red[tid] += red[tid + o];
        __syncthreads();
    }
    const float inv = (e > s) ? 1.f / red[0] : 0.f;

    float acc = 0.f;
    for (int i = s; i < e; i++) {
        const float alpha = expf(__ldg(&gate[i]) - mm) * inv;
        acc += alpha * __half2float(F[(size_t)i * D + tid]);
    }
    Z[g * D + tid] = acc;
}

// g_agg = Z@attW + attb ; out = relu(g_agg@glW_top + glb)
__global__ __launch_bounds__(256)
void final_g2(const float* __restrict__ Z, const float* __restrict__ attW,
              const float* __restrict__ attb, const float* __restrict__ glW,
              const float* __restrict__ glb, float* __restrict__ out)
{
    __shared__ float zrow[D];
    __shared__ float arow[D];
    const int g = blockIdx.x, c = threadIdx.x;
    zrow[c] = Z[g * D + c];
    __syncthreads();
    float t = attb[c];
#pragma unroll 8
    for (int k = 0; k < D; k++) t += zrow[k] * attW[(size_t)k * D + c];
    arow[c] = t;
    __syncthreads();
    float s = glb[c];
#pragma unroll 8
    for (int k = 0; k < D; k++) s += arow[k] * glW[(size_t)k * D + c];
    out[(size_t)g * D + c] = fmaxf(s, 0.f);
}

// ---------------------------------------------------------------------------
extern "C" void kernel_launch(void* const* d_in, const int* in_sizes, int n_in,
                              void* d_out, int out_size)
{
    const float* variables = (const float*)d_in[0];
    const float* factors   = (const float*)d_in[1];
    // d_in[2] = edge_attr (unused by the math)
    const int* edge_index  = (const int*)d_in[3];
    const int* batch       = (const int*)d_in[4];
    const float* mW_v2f = (const float*)d_in[5];
    const float* mb_v2f = (const float*)d_in[6];
    const float* cW_v2f = (const float*)d_in[7];
    const float* cb_v2f = (const float*)d_in[8];
    const float* mW_f2v = (const float*)d_in[9];
    const float* mb_f2v = (const float*)d_in[10];
    const float* cW_f2v = (const float*)d_in[11];
    const float* cb_f2v = (const float*)d_in[12];
    const float* gate_W = (const float*)d_in[13];
    const float* gate_b = (const float*)d_in[14];
    const float* att_W  = (const float*)d_in[15];
    const float* att_b  = (const float*)d_in[16];
    const float* gl_W   = (const float*)d_in[17];
    const float* gl_b   = (const float*)d_in[18];

    const int* src = edge_index;        // row 0: variable idx
    const int* dst = edge_index + EE;   // row 1: factor idx

    float* outV = (float*)d_out;
    float* outF = outV + (size_t)NV * D;
    float* outG = outF + (size_t)NF * D;

    __half *hFa, *hFb, *hFh, *hFagg, *hVa, *hVb, *hVh, *hVagg, *hW;
    float *gate, *Z;
    int *cntF, *cntV, *offF, *offV, *curF, *curV, *elF, *elV, *part;
    cudaGetSymbolAddress((void**)&hFa, g_hFa);
    cudaGetSymbolAddress((void**)&hFb, g_hFb);
    cudaGetSymbolAddress((void**)&hFh, g_hFh);
    cudaGetSymbolAddress((void**)&hFagg, g_hFagg);
    cudaGetSymbolAddress((void**)&hVa, g_hVa);
    cudaGetSymbolAddress((void**)&hVb, g_hVb);
    cudaGetSymbolAddress((void**)&hVh, g_hVh);
    cudaGetSymbolAddress((void**)&hVagg, g_hVagg);
    cudaGetSymbolAddress((void**)&hW,  g_hW);
    cudaGetSymbolAddress((void**)&gate, g_gate);
    cudaGetSymbolAddress((void**)&Z,    g_Z);
    cudaGetSymbolAddress((void**)&part, g_part);
    cudaGetSymbolAddress((void**)&cntF, g_cntF);
    cudaGetSymbolAddress((void**)&cntV, g_cntV);
    cudaGetSymbolAddress((void**)&offF, g_offF);
    cudaGetSymbolAddress((void**)&offV, g_offV);
    cudaGetSymbolAddress((void**)&curF, g_curF);
    cudaGetSymbolAddress((void**)&curV, g_curV);
    cudaGetSymbolAddress((void**)&elF,  g_elF);
    cudaGetSymbolAddress((void**)&elV,  g_elV);

    __half* wm_v2f = hW;
    __half* wc_v2f = hW + 262144;
    __half* wm_f2v = hW + 524288;
    __half* wc_f2v = hW + 786432;

    cudaFuncSetAttribute(gemm_single<EP_RELU_BIAS, 512, false>,      cudaFuncAttributeMaxDynamicSharedMemorySize, SMEM_BYTES);
    cudaFuncSetAttribute(gemm_single<EP_RELU_BIAS, 512, true>,       cudaFuncAttributeMaxDynamicSharedMemorySize, SMEM_BYTES);
    cudaFuncSetAttribute(gemm_single<EP_RELU_BIAS_RES, 512, false>,  cudaFuncAttributeMaxDynamicSharedMemorySize, SMEM_BYTES);
    cudaFuncSetAttribute(gemm_single<EP_RELU_BIAS_RES, 512, true>,   cudaFuncAttributeMaxDynamicSharedMemorySize, SMEM_BYTES);
    cudaFuncSetAttribute(gemm_dual<EP_BIAS, EP_NONE>,                cudaFuncAttributeMaxDynamicSharedMemorySize, SMEM_BYTES);

    // ---- convert inputs + weights to half ----
    {
        CvtArgs a;
        a.src[0] = variables; a.dst[0] = hVa;
        a.src[1] = factors;   a.dst[1] = hFa;
        a.src[2] = mW_v2f;    a.dst[2] = wm_v2f;
        a.src[3] = cW_v2f;    a.dst[3] = wc_v2f;
        a.src[4] = mW_f2v;    a.dst[4] = wm_f2v;
        a.src[5] = cW_f2v;    a.dst[5] = wc_f2v;
        const int sz[6] = {NV * D, NF * D, 262144, 262144, 262144, 262144};
        a.off[0] = 0;
        for (int i = 0; i < 6; i++) a.off[i + 1] = a.off[i] + sz[i];
        convert_multi<<<(a.off[6] + 255) / 256, 256>>>(a);
    }

    // ---- CSR build (fused F+V scan chain) ----
    cudaMemsetAsync(cntF, 0, NF * sizeof(int), 0);
    cudaMemsetAsync(cntV, 0, NV * sizeof(int), 0);
    const int eb = (EE + 255) / 256;
    hist_kernel<<<eb, 256>>>(src, dst, cntF, cntV);
    const int nbF = (NF + 255) / 256, nbV = (NV + 255) / 256;
    blk_sum2<<<nbF + nbV, 256>>>(cntF, NF, cntV, NV, nbF, part);
    scan_part2<<<2, 256>>>(part, nbF, nbV, offF + NF, offV + NV);
    scan_apply2<<<nbF + nbV, 256>>>(cntF, NF, cntV, NV, nbF, part,
                                    offF, curF, offV, curV);
    scatter_kernel<<<eb, 256>>>(src, dst, curF, curV, elF, elV);

    const dim3 blk(256);
    const int nYF = (NF + 127) / 128;   // 313
    const int nYV = (NV + 127) / 128;   // 157
    const dim3 gridF(2, nYF);
    const dim3 gridV(2, nYV);
    const dim3 gridDual(2, nYF + nYV);
    const dim3 aggBlk(32, 8);

    __half* Fcur = hFa;  __half* Vcur = hVa;
    __half* Fnxt = hFb;  __half* Vnxt = hVb;

    for (int l = 0; l < 2; l++) {
        // ---- variable -> factor ----
        {
            const __half* mW = wm_v2f + (size_t)l * D2 * D;
            const float* mb = mb_v2f + (size_t)l * D;
            const __half* cW = wc_v2f + (size_t)l * D2 * D;
            const float* cb = cb_v2f + (size_t)l * D;

            gemm_dual<EP_BIAS, EP_NONE><<<gridDual, blk, SMEM_BYTES>>>(
                Fcur, mW, hFh, mb, NF, nYF,
                Vcur, mW + D * D, hVh, NV);
            aggregate<<<(NF + 7) / 8, aggBlk>>>(hFh, hVh, offF, elF, hFagg, NF);
            if (l == 0)
                gemm_single<EP_RELU_BIAS, 512, false><<<gridF, blk, SMEM_BYTES>>>(
                    Fcur, hFagg, cW, Fnxt, cb, nullptr, nullptr, NF);
            else
                gemm_single<EP_RELU_BIAS, 512, true><<<gridF, blk, SMEM_BYTES>>>(
                    Fcur, hFagg, cW, Fnxt, cb, nullptr, outF, NF);
            __half* t = Fcur; Fcur = Fnxt; Fnxt = t;
        }
        // ---- factor -> variable ----
        {
            const __half* mW = wm_f2v + (size_t)l * D2 * D;
            const float* mb = mb_f2v + (size_t)l * D;
            const __half* cW = wc_f2v + (size_t)l * D2 * D;
            const float* cb = cb_f2v + (size_t)l * D;

            gemm_dual<EP_BIAS, EP_NONE><<<gridDual, blk, SMEM_BYTES>>>(
                Vcur, mW, hVh, mb, NV, nYV,
                Fcur, mW + D * D, hFh, NF);
            aggregate<<<(NV + 7) / 8, aggBlk>>>(hVh, hFh, offV, elV, hVagg, NV);
            if (l == 0)
                gemm_single<EP_RELU_BIAS_RES, 512, false><<<gridV, blk, SMEM_BYTES>>>(
                    Vcur, hVagg, cW, Vnxt, cb, Vcur, nullptr, NV);
            else
                gemm_single<EP_RELU_BIAS_RES, 512, true><<<gridV, blk, SMEM_BYTES>>>(
                    Vcur, hVagg, cW, Vnxt, cb, Vcur, outV, NV);
            __half* t = Vcur; Vcur = Vnxt; Vnxt = t;
        }
    }
    // after 2 layers: Fcur == hFa (also in outF), Vcur == hVa (in outV)

    // ---- GlobalNode attention pooling (affine identity: pool F2, then attW) --
    gate_kernel<<<(NF + 7) / 8, 256>>>(Fcur, gate_W, gate_b, gate);
    graph_agg<<<GG, 256>>>(gate, Fcur, batch, Z);
    final_g2<<<GG, 256>>>(Z, att_W, att_b, gl_W, gl_b, outG);
}

// round 14
// speedup vs baseline: 1.3346x; 1.3346x over previous
#include <cuda_runtime.h>
#include <cuda_fp16.h>
#include <math.h>
#include <stdint.h>

#define NV 20000
#define NF 40000
#define EE 320000
#define GG 64
#define D  256
#define D2 512

// ---------------- scratch (device globals; no allocation allowed) ----------
__device__ __half g_hFa[NF * D], g_hFb[NF * D], g_hFh[NF * D], g_hFagg[NF * D];
__device__ __half g_hVa[NV * D], g_hVb[NV * D], g_hVh[NV * D], g_hVagg[NV * D];
__device__ __half g_hW[1114112];
__device__ float g_gate[NF];
__device__ float g_gagg[GG * D];
__device__ int   g_part[512];
// CSR scratch
__device__ int g_cntF[NF], g_cntV[NV];
__device__ int g_offF[NF + 1], g_offV[NV + 1];
__device__ int g_curF[NF], g_curV[NV];
__device__ int g_elF[EE], g_elV[EE];

enum { EP_NONE = 0, EP_BIAS = 1, EP_RELU_BIAS = 2, EP_RELU_BIAS_RES = 3 };

__device__ __forceinline__ uint32_t smem_u32(const void* p) {
    uint32_t a;
    asm("{ .reg .u64 t; cvta.to.shared.u64 t, %1; cvt.u32.u64 %0, t; }"
        : "=r"(a) : "l"(p));
    return a;
}
__device__ __forceinline__ void ldm_x4(unsigned& r0, unsigned& r1,
                                       unsigned& r2, unsigned& r3, uint32_t a) {
    asm volatile("ldmatrix.sync.aligned.m8n8.x4.shared.b16 {%0,%1,%2,%3}, [%4];"
                 : "=r"(r0), "=r"(r1), "=r"(r2), "=r"(r3) : "r"(a));
}
__device__ __forceinline__ void ldm_x4_t(unsigned& r0, unsigned& r1,
                                         unsigned& r2, unsigned& r3, uint32_t a) {
    asm volatile("ldmatrix.sync.aligned.m8n8.x4.trans.shared.b16 {%0,%1,%2,%3}, [%4];"
                 : "=r"(r0), "=r"(r1), "=r"(r2), "=r"(r3) : "r"(a));
}
__device__ __forceinline__ void mma_f16(float* d, const unsigned* a,
                                        const unsigned* b, const float* c) {
    asm volatile(
        "mma.sync.aligned.m16n8k16.row.col.f32.f16.f16.f32 "
        "{%0,%1,%2,%3}, {%4,%5,%6,%7}, {%8,%9}, {%10,%11,%12,%13};"
        : "=f"(d[0]), "=f"(d[1]), "=f"(d[2]), "=f"(d[3])
        : "r"(a[0]), "r"(a[1]), "r"(a[2]), "r"(a[3]),
          "r"(b[0]), "r"(b[1]),
          "f"(c[0]), "f"(c[1]), "f"(c[2]), "f"(c[3]));
}

#define ASH 5120
#define BSH 4352
#define BS_BASE 40960
#define SMEM_BYTES 75776

// ---- GEMM body: C[128x128 tile] = concat-A[M x KTOT] @ W[KTOT x 256] ------
// fp16 in, fp32 accumulate, half out; optional fp32 secondary output.
template <int MODE, int KTOT, bool F32OUT>
__device__ __forceinline__ void gemm_body(
    char* smem,
    const __half* __restrict__ A0, const __half* __restrict__ A1,
    const __half* __restrict__ W, __half* __restrict__ Cout,
    const float* __restrict__ bias, const __half* __restrict__ res,
    float* __restrict__ Cout32,
    int M, int yBlk, int xBlk)
{
    __half* AsB = reinterpret_cast<__half*>(smem);
    __half* BsB = reinterpret_cast<__half*>(smem + BS_BASE);

    const int tid  = threadIdx.x;
    const int wid  = tid >> 5;
    const int lane = tid & 31;
    const int g = lane >> 2;
    const int c = lane & 3;
    const int rowBase = yBlk * 128;
    const int colBase = xBlk * 128;
    const int wr = (wid & 1) * 64;
    const int wc = (wid >> 1) * 32;

    float acc[4][4][4];
#pragma unroll
    for (int i = 0; i < 4; i++)
#pragma unroll
        for (int j = 0; j < 4; j++)
#pragma unroll
            for (int k = 0; k < 4; k++) acc[i][j][k] = 0.f;

    auto issue = [&](int slab) {
        const __half* Asrc = (KTOT == 512 && slab >= 8) ? A1 : A0;
        const int kb = (slab * 32) & 255;
        __half* As = AsB + (slab & 3) * ASH;
        __half* Bs = BsB + (slab & 3) * BSH;
#pragma unroll
        for (int it = 0; it < 2; it++) {
            const int id = it * 256 + tid;
            const int r = id >> 2, kq = id & 3;
            const int gr = rowBase + r;
            const int grc = (gr < M) ? gr : (M - 1);
            const __half* src = &Asrc[(size_t)grc * D + kb + kq * 8];
            const uint32_t dst = smem_u32(As + r * 40 + kq * 8);
            const int sz = (gr < M) ? 16 : 0;
            asm volatile("cp.async.cg.shared.global [%0], [%1], 16, %2;\n"
                         :: "r"(dst), "l"(src), "r"(sz) : "memory");
        }
#pragma unroll
        for (int it = 0; it < 2; it++) {
            const int id = it * 256 + tid;
            const int kk = id >> 4, n8 = (id & 15) * 8;
            const __half* src = &W[(size_t)(slab * 32 + kk) * D + colBase + n8];
            const uint32_t dst = smem_u32(Bs + kk * 136 + n8);
            asm volatile("cp.async.cg.shared.global [%0], [%1], 16;\n"
                         :: "r"(dst), "l"(src) : "memory");
        }
        asm volatile("cp.async.commit_group;\n" ::: "memory");
    };

    constexpr int NSLAB = KTOT / 32;
    issue(0); issue(1); issue(2);

    for (int s = 0; s < NSLAB; s++) {
        asm volatile("cp.async.wait_group 2;\n" ::: "memory");
        __syncthreads();
        if (s + 3 < NSLAB) issue(s + 3);

        const uint32_t aBase = smem_u32(AsB + (s & 3) * ASH);
        const uint32_t bBase = smem_u32(BsB + (s & 3) * BSH);
#pragma unroll
        for (int ks = 0; ks < 32; ks += 16) {
            unsigned a[4][4], b[4][2];
#pragma unroll
            for (int mf = 0; mf < 4; mf++) {
                const uint32_t addr = aBase +
                    (((wr + mf * 16 + (lane & 15)) * 40 + ks + (lane >> 4) * 8) << 1);
                ldm_x4(a[mf][0], a[mf][1], a[mf][2], a[mf][3], addr);
            }
#pragma unroll
            for (int p = 0; p < 2; p++) {
                const uint32_t addr = bBase +
                    ((((ks + (lane & 7) + ((lane >> 3) & 1) * 8)) * 136 +
                      wc + p * 16 + (lane >> 4) * 8) << 1);
                ldm_x4_t(b[2 * p][0], b[2 * p][1], b[2 * p + 1][0], b[2 * p + 1][1], addr);
            }
#pragma unroll
            for (int mf = 0; mf < 4; mf++)
#pragma unroll
                for (int nf = 0; nf < 4; nf++)
                    mma_f16(acc[mf][nf], a[mf], b[nf], acc[mf][nf]);
        }
    }

#pragma unroll
    for (int mf = 0; mf < 4; mf++) {
#pragma unroll
        for (int half = 0; half < 2; half++) {
            const int r = rowBase + wr + mf * 16 + g + half * 8;
            if (r >= M) continue;
#pragma unroll
            for (int nf = 0; nf < 4; nf++) {
                const int col = colBase + wc + nf * 8 + 2 * c;
                float2 v = make_float2(acc[mf][nf][half * 2], acc[mf][nf][half * 2 + 1]);
                if (MODE == EP_BIAS) {
                    v.x += bias[col + 0];
                    v.y += bias[col + 1];
                } else if (MODE == EP_RELU_BIAS || MODE == EP_RELU_BIAS_RES) {
                    v.x = fmaxf(v.x + bias[col + 0], 0.f);
                    v.y = fmaxf(v.y + bias[col + 1], 0.f);
                    if (MODE == EP_RELU_BIAS_RES) {
                        const __half2 rr = *reinterpret_cast<const __half2*>(&res[(size_t)r * D + col]);
                        const float2 rf = __half22float2(rr);
                        v.x += rf.x; v.y += rf.y;
                    }
                }
                *reinterpret_cast<__half2*>(&Cout[(size_t)r * D + col]) =
                    __floats2half2_rn(v.x, v.y);
                if (F32OUT) {
                    // match half-rounded state so pooling (half) and output agree
                    const float2 hf = __half22float2(__floats2half2_rn(v.x, v.y));
                    *reinterpret_cast<float2*>(&Cout32[(size_t)r * D + col]) = hf;
                }
            }
        }
    }
}

template <int MODE, int KTOT, bool F32OUT>
__global__ __launch_bounds__(256, 2)
void gemm_single(const __half* __restrict__ A0, const __half* __restrict__ A1,
                 const __half* __restrict__ W, __half* __restrict__ Cout,
                 const float* __restrict__ bias, const __half* __restrict__ res,
                 float* __restrict__ Cout32, int M)
{
    extern __shared__ char smem[];
    gemm_body<MODE, KTOT, F32OUT>(smem, A0, A1, W, Cout, bias, res, Cout32, M,
                                  blockIdx.y, blockIdx.x);
}

template <int MODEA, int MODEB>
__global__ __launch_bounds__(256, 2)
void gemm_dual(const __half* __restrict__ Aa, const __half* __restrict__ Wa,
               __half* __restrict__ Ca, const float* __restrict__ biasa,
               int Ma, int nYa,
               const __half* __restrict__ Ab, const __half* __restrict__ Wb,
               __half* __restrict__ Cb, int Mb)
{
    extern __shared__ char smem[];
    if ((int)blockIdx.y < nYa)
        gemm_body<MODEA, 256, false>(smem, Aa, nullptr, Wa, Ca, biasa, nullptr,
                                     nullptr, Ma, blockIdx.y, blockIdx.x);
    else
        gemm_body<MODEB, 256, false>(smem, Ab, nullptr, Wb, Cb, nullptr, nullptr,
                                     nullptr, Mb, blockIdx.y - nYa, blockIdx.x);
}

// ---------------- batched fp32 -> fp16 convert -------------------------------
struct CvtArgs {
    const float* src[7];
    __half* dst[7];
    int off[8];
};
__global__ __launch_bounds__(256)
void convert_multi(CvtArgs a)
{
    const int i = blockIdx.x * 256 + threadIdx.x;
    if (i >= a.off[7]) return;
    int s = 0;
    while (i >= a.off[s + 1]) s++;
    const int j = i - a.off[s];
    a.dst[s][j] = __float2half_rn(__ldg(&a.src[s][j]));
}

// ---------------- CSR build --------------------------------------------------
__global__ __launch_bounds__(256)
void hist_kernel(const int* __restrict__ src, const int* __restrict__ dst,
                 int* cntF, int* cntV)
{
    const int e = blockIdx.x * 256 + threadIdx.x;
    if (e >= EE) return;
    atomicAdd(&cntF[__ldg(&dst[e])], 1);
    atomicAdd(&cntV[__ldg(&src[e])], 1);
}

// fused F+V hierarchical scan: both count arrays handled per launch.
// part layout: F partials at part[0..nbF), V partials at part[256..256+nbV).
__global__ __launch_bounds__(256)
void blk_sum2(const int* __restrict__ cntF, int nF, const int* __restrict__ cntV,
              int nV, int nbF, int* __restrict__ part)
{
    const bool isV = (int)blockIdx.x >= nbF;
    const int b = isV ? (blockIdx.x - nbF) : blockIdx.x;
    const int* cnt = isV ? cntV : cntF;
    const int n = isV ? nV : nF;
    const int i = b * 256 + threadIdx.x;
    int x = (i < n) ? cnt[i] : 0;
#pragma unroll
    for (int o = 16; o > 0; o >>= 1) x += __shfl_xor_sync(0xffffffffu, x, o);
    __shared__ int ws[8];
    if ((threadIdx.x & 31) == 0) ws[threadIdx.x >> 5] = x;
    __syncthreads();
    if (threadIdx.x == 0) {
        int t = 0;
#pragma unroll
        for (int q = 0; q < 8; q++) t += ws[q];
        part[(isV ? 256 : 0) + b] = t;
    }
}

__global__ __launch_bounds__(256)
void scan_part2(int* __restrict__ part, int nbF, int nbV,
                int* __restrict__ totF, int* __restrict__ totV)
{
    const bool isV = blockIdx.x == 1;
    int* p = part + (isV ? 256 : 0);
    const int nb = isV ? nbV : nbF;
    int* total_out = isV ? totV : totF;
    const int t = threadIdx.x, lane = t & 31, w = t >> 5;
    const int x = (t < nb) ? p[t] : 0;
    int incl = x;
#pragma unroll
    for (int o = 1; o < 32; o <<= 1) {
        const int v = __shfl_up_sync(0xffffffffu, incl, o);
        if (lane >= o) incl += v;
    }
    __shared__ int ws[8], wex[8];
    if (lane == 31) ws[w] = incl;
    __syncthreads();
    if (t == 0) {
        int s = 0;
#pragma unroll
        for (int q = 0; q < 8; q++) { wex[q] = s; s += ws[q]; }
        total_out[0] = s;
    }
    __syncthreads();
    if (t < nb) p[t] = wex[w] + incl - x;
}

__global__ __launch_bounds__(256)
void scan_apply2(const int* __restrict__ cntF, int nF,
                 const int* __restrict__ cntV, int nV, int nbF,
                 const int* __restrict__ part,
                 int* __restrict__ offF, int* __restrict__ curF,
                 int* __restrict__ offV, int* __restrict__ curV)
{
    const bool isV = (int)blockIdx.x >= nbF;
    const int b = isV ? (blockIdx.x - nbF) : blockIdx.x;
    const int* cnt = isV ? cntV : cntF;
    const int n = isV ? nV : nF;
    int* off = isV ? offV : offF;
    int* cur = isV ? curV : curF;
    const int base = isV ? 256 : 0;
    const int i = b * 256 + threadIdx.x;
    const int t = threadIdx.x, lane = t & 31, w = t >> 5;
    const int x = (i < n) ? cnt[i] : 0;
    int incl = x;
#pragma unroll
    for (int o = 1; o < 32; o <<= 1) {
        const int v = __shfl_up_sync(0xffffffffu, incl, o);
        if (lane >= o) incl += v;
    }
    __shared__ int ws[8], wex[8];
    if (lane == 31) ws[w] = incl;
    __syncthreads();
    if (t == 0) {
        int s = 0;
#pragma unroll
        for (int q = 0; q < 8; q++) { wex[q] = s; s += ws[q]; }
    }
    __syncthreads();
    const int ex = part[base + b] + wex[w] + incl - x;
    if (i < n) { off[i] = ex; cur[i] = ex; }
}

__global__ __launch_bounds__(256)
void scatter_kernel(const int* __restrict__ src, const int* __restrict__ dst,
                    int* curF, int* curV, int* elF, int* elV)
{
    const int e = blockIdx.x * 256 + threadIdx.x;
    if (e >= EE) return;
    const int s = __ldg(&src[e]);
    const int d2 = __ldg(&dst[e]);
    elF[atomicAdd(&curF[d2], 1)] = s;
    elV[atomicAdd(&curV[s], 1)] = d2;
}

// ---------------- CSR gather-aggregate (half in, half out) -------------------
__global__ __launch_bounds__(256)
void aggregate(const __half* __restrict__ Hself, const __half* __restrict__ Hother,
               const int* __restrict__ off, const int* __restrict__ elist,
               __half* __restrict__ out, int n)
{
    const int row = blockIdx.x * 8 + threadIdx.y;
    if (row >= n) return;
    const int d = threadIdx.x * 8;
    const __half2* sp = reinterpret_cast<const __half2*>(&Hself[(size_t)row * D + d]);
    float2 s0 = __half22float2(sp[0]), s1 = __half22float2(sp[1]);
    float2 s2 = __half22float2(sp[2]), s3 = __half22float2(sp[3]);
    float a0x = 0.f, a0y = 0.f, a1x = 0.f, a1y = 0.f;
    float a2x = 0.f, a2y = 0.f, a3x = 0.f, a3y = 0.f;
    int j = __ldg(&off[row]);
    const int e = __ldg(&off[row + 1]);
    for (; j < e; j++) {
        const int o = __ldg(&elist[j]);
        const __half2* op = reinterpret_cast<const __half2*>(&Hother[(size_t)o * D + d]);
        const float2 v0 = __half22float2(op[0]), v1 = __half22float2(op[1]);
        const float2 v2 = __half22float2(op[2]), v3 = __half22float2(op[3]);
        a0x += fmaxf(s0.x + v0.x, 0.f); a0y += fmaxf(s0.y + v0.y, 0.f);
        a1x += fmaxf(s1.x + v1.x, 0.f); a1y += fmaxf(s1.y + v1.y, 0.f);
        a2x += fmaxf(s2.x + v2.x, 0.f); a2y += fmaxf(s2.y + v2.y, 0.f);
        a3x += fmaxf(s3.x + v3.x, 0.f); a3y += fmaxf(s3.y + v3.y, 0.f);
    }
    __half2* op2 = reinterpret_cast<__half2*>(&out[(size_t)row * D + d]);
    op2[0] = __floats2half2_rn(a0x, a0y);
    op2[1] = __floats2half2_rn(a1x, a1y);
    op2[2] = __floats2half2_rn(a2x, a2y);
    op2[3] = __floats2half2_rn(a3x, a3y);
}

// ---------------- attention pooling -----------------------------------------
__global__ __launch_bounds__(256)
void gate_kernel(const __half* __restrict__ F, const float* __restrict__ gW,
                 const float* __restrict__ gb, float* __restrict__ gate)
{
    const int w = threadIdx.x >> 5, lane = threadIdx.x & 31;
    const int row = blockIdx.x * 8 + w;
    if (row >= NF) return;
    float s = 0.f;
#pragma unroll
    for (int i = 0; i < 8; i++) {
        const int k = lane + i * 32;
        s += __half2float(F[(size_t)row * D + k]) * __ldg(&gW[k]);
    }
#pragma unroll
    for (int o = 16; o > 0; o >>= 1) s += __shfl_xor_sync(0xffffffff, s, o);
    if (lane == 0) gate[row] = s + gb[0];
}

__device__ __forceinline__ int lbound(const int* __restrict__ a, int n, int v)
{
    int lo = 0, hi = n;
    while (lo < hi) {
        const int mid = (lo + hi) >> 1;
        if (a[mid] < v) lo = mid + 1; else hi = mid;
    }
    return lo;
}

__global__ __launch_bounds__(256)
void graph_agg(const float* __restrict__ gate, const __half* __restrict__ T,
               const int* __restrict__ batch, float* __restrict__ gagg)
{
    __shared__ float red[256];
    __shared__ int sse[2];
    const int g = blockIdx.x, tid = threadIdx.x;
    if (tid == 0) sse[0] = lbound(batch, NF, g);
    if (tid == 1) sse[1] = lbound(batch, NF, g + 1);
    __syncthreads();
    const int s = sse[0], e = sse[1];

    float m = -INFINITY;
    for (int i = s + tid; i < e; i += 256) m = fmaxf(m, __ldg(&gate[i]));
    red[tid] = m; __syncthreads();
    for (int o = 128; o > 0; o >>= 1) {
        if (tid < o) red[tid] = fmaxf(red[tid], red[tid + o]);
        __syncthreads();
    }
    const float mm = red[0]; __syncthreads();

    float sum = 0.f;
    for (int i = s + tid; i < e; i += 256) sum += expf(__ldg(&gate[i]) - mm);
    red[tid] = sum; __syncthreads();
    for (int o = 128; o > 0; o >>= 1) {
        if (tid < o) red[tid] += red[tid + o];
        __syncthreads();
    }
    const float inv = (e > s) ? 1.f / red[0] : 0.f;

    float acc = 0.f;
    for (int i = s; i < e; i++) {
        const float alpha = expf(__ldg(&gate[i]) - mm) * inv;
        acc += alpha * __half2float(T[(size_t)i * D + tid]);
    }
    gagg[g * D + tid] = acc;
}

__global__ __launch_bounds__(256)
void final_g(const float* __restrict__ gagg, const float* __restrict__ glW,
             const float* __restrict__ glb, float* __restrict__ out)
{
    __shared__ float row[D];
    const int g = blockIdx.x, c = threadIdx.x;
    row[c] = gagg[g * D + c];
    __syncthreads();
    float s = glb[c];
#pragma unroll 8
    for (int k = 0; k < D; k++) s += row[k] * glW[(size_t)k * D + c];
    out[(size_t)g * D + c] = fmaxf(s, 0.f);
}

// ---------------------------------------------------------------------------
extern "C" void kernel_launch(void* const* d_in, const int* in_sizes, int n_in,
                              void* d_out, int out_size)
{
    const float* variables = (const float*)d_in[0];
    const float* factors   = (const float*)d_in[1];
    // d_in[2] = edge_attr (unused by the math)
    const int* edge_index  = (const int*)d_in[3];
    const int* batch       = (const int*)d_in[4];
    const float* mW_v2f = (const float*)d_in[5];
    const float* mb_v2f = (const float*)d_in[6];
    const float* cW_v2f = (const float*)d_in[7];
    const float* cb_v2f = (const float*)d_in[8];
    const float* mW_f2v = (const float*)d_in[9];
    const float* mb_f2v = (const float*)d_in[10];
    const float* cW_f2v = (const float*)d_in[11];
    const float* cb_f2v = (const float*)d_in[12];
    const float* gate_W = (const float*)d_in[13];
    const float* gate_b = (const float*)d_in[14];
    const float* att_W  = (const float*)d_in[15];
    const float* att_b  = (const float*)d_in[16];
    const float* gl_W   = (const float*)d_in[17];
    const float* gl_b   = (const float*)d_in[18];

    const int* src = edge_index;        // row 0: variable idx
    const int* dst = edge_index + EE;   // row 1: factor idx

    float* outV = (float*)d_out;
    float* outF = outV + (size_t)NV * D;
    float* outG = outF + (size_t)NF * D;

    __half *hFa, *hFb, *hFh, *hFagg, *hVa, *hVb, *hVh, *hVagg, *hW;
    float *gate, *gagg;
    int *cntF, *cntV, *offF, *offV, *curF, *curV, *elF, *elV, *part;
    cudaGetSymbolAddress((void**)&hFa, g_hFa);
    cudaGetSymbolAddress((void**)&hFb, g_hFb);
    cudaGetSymbolAddress((void**)&hFh, g_hFh);
    cudaGetSymbolAddress((void**)&hFagg, g_hFagg);
    cudaGetSymbolAddress((void**)&hVa, g_hVa);
    cudaGetSymbolAddress((void**)&hVb, g_hVb);
    cudaGetSymbolAddress((void**)&hVh, g_hVh);
    cudaGetSymbolAddress((void**)&hVagg, g_hVagg);
    cudaGetSymbolAddress((void**)&hW,  g_hW);
    cudaGetSymbolAddress((void**)&gate, g_gate);
    cudaGetSymbolAddress((void**)&gagg, g_gagg);
    cudaGetSymbolAddress((void**)&part, g_part);
    cudaGetSymbolAddress((void**)&cntF, g_cntF);
    cudaGetSymbolAddress((void**)&cntV, g_cntV);
    cudaGetSymbolAddress((void**)&offF, g_offF);
    cudaGetSymbolAddress((void**)&offV, g_offV);
    cudaGetSymbolAddress((void**)&curF, g_curF);
    cudaGetSymbolAddress((void**)&curV, g_curV);
    cudaGetSymbolAddress((void**)&elF,  g_elF);
    cudaGetSymbolAddress((void**)&elV,  g_elV);

    __half* wm_v2f = hW;
    __half* wc_v2f = hW + 262144;
    __half* wm_f2v = hW + 524288;
    __half* wc_f2v = hW + 786432;
    __half* watt   = hW + 1048576;

    cudaFuncSetAttribute(gemm_single<EP_BIAS, 256, false>,           cudaFuncAttributeMaxDynamicSharedMemorySize, SMEM_BYTES);
    cudaFuncSetAttribute(gemm_single<EP_NONE, 256, false>,           cudaFuncAttributeMaxDynamicSharedMemorySize, SMEM_BYTES);
    cudaFuncSetAttribute(gemm_single<EP_RELU_BIAS, 512, false>,      cudaFuncAttributeMaxDynamicSharedMemorySize, SMEM_BYTES);
    cudaFuncSetAttribute(gemm_single<EP_RELU_BIAS, 512, true>,       cudaFuncAttributeMaxDynamicSharedMemorySize, SMEM_BYTES);
    cudaFuncSetAttribute(gemm_single<EP_RELU_BIAS_RES, 512, false>,  cudaFuncAttributeMaxDynamicSharedMemorySize, SMEM_BYTES);
    cudaFuncSetAttribute(gemm_single<EP_RELU_BIAS_RES, 512, true>,   cudaFuncAttributeMaxDynamicSharedMemorySize, SMEM_BYTES);
    cudaFuncSetAttribute(gemm_dual<EP_BIAS, EP_NONE>,                cudaFuncAttributeMaxDynamicSharedMemorySize, SMEM_BYTES);

    // ---- convert inputs + weights to half ----
    {
        CvtArgs a;
        a.src[0] = variables; a.dst[0] = hVa;
        a.src[1] = factors;   a.dst[1] = hFa;
        a.src[2] = mW_v2f;    a.dst[2] = wm_v2f;
        a.src[3] = cW_v2f;    a.dst[3] = wc_v2f;
        a.src[4] = mW_f2v;    a.dst[4] = wm_f2v;
        a.src[5] = cW_f2v;    a.dst[5] = wc_f2v;
        a.src[6] = att_W;     a.dst[6] = watt;
        const int sz[7] = {NV * D, NF * D, 262144, 262144, 262144, 262144, 65536};
        a.off[0] = 0;
        for (int i = 0; i < 7; i++) a.off[i + 1] = a.off[i] + sz[i];
        convert_multi<<<(a.off[7] + 255) / 256, 256>>>(a);
    }

    // ---- CSR build (fused F+V scan chain) ----
    cudaMemsetAsync(cntF, 0, NF * sizeof(int), 0);
    cudaMemsetAsync(cntV, 0, NV * sizeof(int), 0);
    const int eb = (EE + 255) / 256;
    hist_kernel<<<eb, 256>>>(src, dst, cntF, cntV);
    const int nbF = (NF + 255) / 256, nbV = (NV + 255) / 256;   // 157, 79
    blk_sum2<<<nbF + nbV, 256>>>(cntF, NF, cntV, NV, nbF, part);
    scan_part2<<<2, 256>>>(part, nbF, nbV, offF + NF, offV + NV);
    scan_apply2<<<nbF + nbV, 256>>>(cntF, NF, cntV, NV, nbF, part,
                                    offF, curF, offV, curV);
    scatter_kernel<<<eb, 256>>>(src, dst, curF, curV, elF, elV);

    const dim3 blk(256);
    const int nYF = (NF + 127) / 128;   // 313
    const int nYV = (NV + 127) / 128;   // 157
    const dim3 gridF(2, nYF);
    const dim3 gridV(2, nYV);
    const dim3 gridDual(2, nYF + nYV);
    const dim3 aggBlk(32, 8);

    __half* Fcur = hFa;  __half* Vcur = hVa;
    __half* Fnxt = hFb;  __half* Vnxt = hVb;

    for (int l = 0; l < 2; l++) {
        // ---- variable -> factor ----
        {
            const __half* mW = wm_v2f + (size_t)l * D2 * D;
            const float* mb = mb_v2f + (size_t)l * D;
            const __half* cW = wc_v2f + (size_t)l * D2 * D;
            const float* cb = cb_v2f + (size_t)l * D;

            gemm_dual<EP_BIAS, EP_NONE><<<gridDual, blk, SMEM_BYTES>>>(
                Fcur, mW, hFh, mb, NF, nYF,
                Vcur, mW + D * D, hVh, NV);
            aggregate<<<(NF + 7) / 8, aggBlk>>>(hFh, hVh, offF, elF, hFagg, NF);
            if (l == 0)
                gemm_single<EP_RELU_BIAS, 512, false><<<gridF, blk, SMEM_BYTES>>>(
                    Fcur, hFagg, cW, Fnxt, cb, nullptr, nullptr, NF);
            else
                gemm_single<EP_RELU_BIAS, 512, true><<<gridF, blk, SMEM_BYTES>>>(
                    Fcur, hFagg, cW, Fnxt, cb, nullptr, outF, NF);
            __half* t = Fcur; Fcur = Fnxt; Fnxt = t;
        }
        // ---- factor -> variable ----
        {
            const __half* mW = wm_f2v + (size_t)l * D2 * D;
            const float* mb = mb_f2v + (size_t)l * D;
            const __half* cW = wc_f2v + (size_t)l * D2 * D;
            const float* cb = cb_f2v + (size_t)l * D;

            gemm_dual<EP_BIAS, EP_NONE><<<gridDual, blk, SMEM_BYTES>>>(
                Vcur, mW, hVh, mb, NV, nYV,
                Fcur, mW + D * D, hFh, NF);
            aggregate<<<(NV + 7) / 8, aggBlk>>>(hVh, hFh, offV, elV, hVagg, NV);
            if (l == 0)
                gemm_single<EP_RELU_BIAS_RES, 512, false><<<gridV, blk, SMEM_BYTES>>>(
                    Vcur, hVagg, cW, Vnxt, cb, Vcur, nullptr, NV);
            else
                gemm_single<EP_RELU_BIAS_RES, 512, true><<<gridV, blk, SMEM_BYTES>>>(
                    Vcur, hVagg, cW, Vnxt, cb, Vcur, outV, NV);
            __half* t = Vcur; Vcur = Vnxt; Vnxt = t;
        }
    }
    // after 2 layers: Fcur == hFa (== F2, also in outF), Vcur == hVa (in outV)

    // ---- GlobalNode attention pooling ----
    gate_kernel<<<(NF + 7) / 8, 256>>>(Fcur, gate_W, gate_b, gate);
    gemm_single<EP_BIAS, 256, false><<<gridF, blk, SMEM_BYTES>>>(
        Fcur, nullptr, watt, hFh, att_b, nullptr, nullptr, NF);
    graph_agg<<<GG, 256>>>(gate, hFh, batch, gagg);
    final_g<<<GG, 256>>>(gagg, gl_W, gl_b, outG);
}

// round 15
// speedup vs baseline: 1.3548x; 1.0152x over previous
#include <cuda_runtime.h>
#include <cuda_fp16.h>
#include <math.h>
#include <stdint.h>

#define NV 20000
#define NF 40000
#define EE 320000
#define GG 64
#define D  256
#define D2 512

// ---------------- scratch (device globals; no allocation allowed) ----------
__device__ __half g_hFa[NF * D], g_hFb[NF * D], g_hFh[NF * D], g_hFagg[NF * D];
__device__ __half g_hVa[NV * D], g_hVb[NV * D], g_hVh[NV * D], g_hVagg[NV * D];
__device__ __half g_hW[1114112];
__device__ float g_gate[NF];
__device__ float g_gagg[GG * D];
__device__ int   g_part[512];
// CSR scratch
__device__ int g_cntF[NF], g_cntV[NV];
__device__ int g_offF[NF + 1], g_offV[NV + 1];
__device__ int g_curF[NF], g_curV[NV];
__device__ int g_elF[EE], g_elV[EE];

enum { EP_NONE = 0, EP_BIAS = 1, EP_RELU_BIAS = 2, EP_RELU_BIAS_RES = 3 };

__device__ __forceinline__ uint32_t smem_u32(const void* p) {
    uint32_t a;
    asm("{ .reg .u64 t; cvta.to.shared.u64 t, %1; cvt.u32.u64 %0, t; }"
        : "=r"(a) : "l"(p));
    return a;
}
__device__ __forceinline__ void ldm_x4(unsigned& r0, unsigned& r1,
                                       unsigned& r2, unsigned& r3, uint32_t a) {
    asm volatile("ldmatrix.sync.aligned.m8n8.x4.shared.b16 {%0,%1,%2,%3}, [%4];"
                 : "=r"(r0), "=r"(r1), "=r"(r2), "=r"(r3) : "r"(a));
}
__device__ __forceinline__ void ldm_x4_t(unsigned& r0, unsigned& r1,
                                         unsigned& r2, unsigned& r3, uint32_t a) {
    asm volatile("ldmatrix.sync.aligned.m8n8.x4.trans.shared.b16 {%0,%1,%2,%3}, [%4];"
                 : "=r"(r0), "=r"(r1), "=r"(r2), "=r"(r3) : "r"(a));
}
__device__ __forceinline__ void mma_f16(float* d, const unsigned* a,
                                        const unsigned* b, const float* c) {
    asm volatile(
        "mma.sync.aligned.m16n8k16.row.col.f32.f16.f16.f32 "
        "{%0,%1,%2,%3}, {%4,%5,%6,%7}, {%8,%9}, {%10,%11,%12,%13};"
        : "=f"(d[0]), "=f"(d[1]), "=f"(d[2]), "=f"(d[3])
        : "r"(a[0]), "r"(a[1]), "r"(a[2]), "r"(a[3]),
          "r"(b[0]), "r"(b[1]),
          "f"(c[0]), "f"(c[1]), "f"(c[2]), "f"(c[3]));
}

#define ASH 5120
#define BSH 4352
#define BS_BASE 40960
#define SMEM_BYTES 75776

// ---- GEMM body: C[128x128 tile] = concat-A[M x KTOT] @ W[KTOT x 256] ------
// fp16 in, fp32 accumulate, half out; optional fp32 secondary output.
template <int MODE, int KTOT, bool F32OUT>
__device__ __forceinline__ void gemm_body(
    char* smem,
    const __half* __restrict__ A0, const __half* __restrict__ A1,
    const __half* __restrict__ W, __half* __restrict__ Cout,
    const float* __restrict__ bias, const __half* __restrict__ res,
    float* __restrict__ Cout32,
    int M, int yBlk, int xBlk)
{
    __half* AsB = reinterpret_cast<__half*>(smem);
    __half* BsB = reinterpret_cast<__half*>(smem + BS_BASE);

    const int tid  = threadIdx.x;
    const int wid  = tid >> 5;
    const int lane = tid & 31;
    const int g = lane >> 2;
    const int c = lane & 3;
    const int rowBase = yBlk * 128;
    const int colBase = xBlk * 128;
    const int wr = (wid & 1) * 64;
    const int wc = (wid >> 1) * 32;

    float acc[4][4][4];
#pragma unroll
    for (int i = 0; i < 4; i++)
#pragma unroll
        for (int j = 0; j < 4; j++)
#pragma unroll
            for (int k = 0; k < 4; k++) acc[i][j][k] = 0.f;

    auto issue = [&](int slab) {
        const __half* Asrc = (KTOT == 512 && slab >= 8) ? A1 : A0;
        const int kb = (slab * 32) & 255;
        __half* As = AsB + (slab & 3) * ASH;
        __half* Bs = BsB + (slab & 3) * BSH;
#pragma unroll
        for (int it = 0; it < 2; it++) {
            const int id = it * 256 + tid;
            const int r = id >> 2, kq = id & 3;
            const int gr = rowBase + r;
            const int grc = (gr < M) ? gr : (M - 1);
            const __half* src = &Asrc[(size_t)grc * D + kb + kq * 8];
            const uint32_t dst = smem_u32(As + r * 40 + kq * 8);
            const int sz = (gr < M) ? 16 : 0;
            asm volatile("cp.async.cg.shared.global [%0], [%1], 16, %2;\n"
                         :: "r"(dst), "l"(src), "r"(sz) : "memory");
        }
#pragma unroll
        for (int it = 0; it < 2; it++) {
            const int id = it * 256 + tid;
            const int kk = id >> 4, n8 = (id & 15) * 8;
            const __half* src = &W[(size_t)(slab * 32 + kk) * D + colBase + n8];
            const uint32_t dst = smem_u32(Bs + kk * 136 + n8);
            asm volatile("cp.async.cg.shared.global [%0], [%1], 16;\n"
                         :: "r"(dst), "l"(src) : "memory");
        }
        asm volatile("cp.async.commit_group;\n" ::: "memory");
    };

    constexpr int NSLAB = KTOT / 32;
    issue(0); issue(1); issue(2);

    for (int s = 0; s < NSLAB; s++) {
        asm volatile("cp.async.wait_group 2;\n" ::: "memory");
        __syncthreads();
        if (s + 3 < NSLAB) issue(s + 3);

        const uint32_t aBase = smem_u32(AsB + (s & 3) * ASH);
        const uint32_t bBase = smem_u32(BsB + (s & 3) * BSH);
#pragma unroll
        for (int ks = 0; ks < 32; ks += 16) {
            unsigned a[4][4], b[4][2];
#pragma unroll
            for (int mf = 0; mf < 4; mf++) {
                const uint32_t addr = aBase +
                    (((wr + mf * 16 + (lane & 15)) * 40 + ks + (lane >> 4) * 8) << 1);
                ldm_x4(a[mf][0], a[mf][1], a[mf][2], a[mf][3], addr);
            }
#pragma unroll
            for (int p = 0; p < 2; p++) {
                const uint32_t addr = bBase +
                    ((((ks + (lane & 7) + ((lane >> 3) & 1) * 8)) * 136 +
                      wc + p * 16 + (lane >> 4) * 8) << 1);
                ldm_x4_t(b[2 * p][0], b[2 * p][1], b[2 * p + 1][0], b[2 * p + 1][1], addr);
            }
#pragma unroll
            for (int mf = 0; mf < 4; mf++)
#pragma unroll
                for (int nf = 0; nf < 4; nf++)
                    mma_f16(acc[mf][nf], a[mf], b[nf], acc[mf][nf]);
        }
    }

#pragma unroll
    for (int mf = 0; mf < 4; mf++) {
#pragma unroll
        for (int half = 0; half < 2; half++) {
            const int r = rowBase + wr + mf * 16 + g + half * 8;
            if (r >= M) continue;
#pragma unroll
            for (int nf = 0; nf < 4; nf++) {
                const int col = colBase + wc + nf * 8 + 2 * c;
                float2 v = make_float2(acc[mf][nf][half * 2], acc[mf][nf][half * 2 + 1]);
                if (MODE == EP_BIAS) {
                    v.x += bias[col + 0];
                    v.y += bias[col + 1];
                } else if (MODE == EP_RELU_BIAS || MODE == EP_RELU_BIAS_RES) {
                    v.x = fmaxf(v.x + bias[col + 0], 0.f);
                    v.y = fmaxf(v.y + bias[col + 1], 0.f);
                    if (MODE == EP_RELU_BIAS_RES) {
                        const __half2 rr = *reinterpret_cast<const __half2*>(&res[(size_t)r * D + col]);
                        const float2 rf = __half22float2(rr);
                        v.x += rf.x; v.y += rf.y;
                    }
                }
                *reinterpret_cast<__half2*>(&Cout[(size_t)r * D + col]) =
                    __floats2half2_rn(v.x, v.y);
                if (F32OUT) {
                    // match half-rounded state so pooling (half) and output agree
                    const float2 hf = __half22float2(__floats2half2_rn(v.x, v.y));
                    *reinterpret_cast<float2*>(&Cout32[(size_t)r * D + col]) = hf;
                }
            }
        }
    }
}

template <int MODE, int KTOT, bool F32OUT>
__global__ __launch_bounds__(256, 2)
void gemm_single(const __half* __restrict__ A0, const __half* __restrict__ A1,
                 const __half* __restrict__ W, __half* __restrict__ Cout,
                 const float* __restrict__ bias, const __half* __restrict__ res,
                 float* __restrict__ Cout32, int M)
{
    extern __shared__ char smem[];
    gemm_body<MODE, KTOT, F32OUT>(smem, A0, A1, W, Cout, bias, res, Cout32, M,
                                  blockIdx.y, blockIdx.x);
}

template <int MODEA, int MODEB>
__global__ __launch_bounds__(256, 2)
void gemm_dual(const __half* __restrict__ Aa, const __half* __restrict__ Wa,
               __half* __restrict__ Ca, const float* __restrict__ biasa,
               int Ma, int nYa,
               const __half* __restrict__ Ab, const __half* __restrict__ Wb,
               __half* __restrict__ Cb, int Mb)
{
    extern __shared__ char smem[];
    if ((int)blockIdx.y < nYa)
        gemm_body<MODEA, 256, false>(smem, Aa, nullptr, Wa, Ca, biasa, nullptr,
                                     nullptr, Ma, blockIdx.y, blockIdx.x);
    else
        gemm_body<MODEB, 256, false>(smem, Ab, nullptr, Wb, Cb, nullptr, nullptr,
                                     nullptr, Mb, blockIdx.y - nYa, blockIdx.x);
}

// ---------------- batched fp32 -> fp16 convert -------------------------------
struct CvtArgs {
    const float* src[7];
    __half* dst[7];
    int off[8];
};
__global__ __launch_bounds__(256)
void convert_multi(CvtArgs a)
{
    const int i = blockIdx.x * 256 + threadIdx.x;
    if (i >= a.off[7]) return;
    int s = 0;
    while (i >= a.off[s + 1]) s++;
    const int j = i - a.off[s];
    a.dst[s][j] = __float2half_rn(__ldg(&a.src[s][j]));
}

// ---------------- CSR build --------------------------------------------------
__global__ __launch_bounds__(256)
void hist_kernel(const int* __restrict__ src, const int* __restrict__ dst,
                 int* cntF, int* cntV)
{
    const int e = blockIdx.x * 256 + threadIdx.x;
    if (e >= EE) return;
    atomicAdd(&cntF[__ldg(&dst[e])], 1);
    atomicAdd(&cntV[__ldg(&src[e])], 1);
}

// fused F+V hierarchical scan: both count arrays handled per launch.
// part layout: F partials at part[0..nbF), V partials at part[256..256+nbV).
__global__ __launch_bounds__(256)
void blk_sum2(const int* __restrict__ cntF, int nF, const int* __restrict__ cntV,
              int nV, int nbF, int* __restrict__ part)
{
    const bool isV = (int)blockIdx.x >= nbF;
    const int b = isV ? (blockIdx.x - nbF) : blockIdx.x;
    const int* cnt = isV ? cntV : cntF;
    const int n = isV ? nV : nF;
    const int i = b * 256 + threadIdx.x;
    int x = (i < n) ? cnt[i] : 0;
#pragma unroll
    for (int o = 16; o > 0; o >>= 1) x += __shfl_xor_sync(0xffffffffu, x, o);
    __shared__ int ws[8];
    if ((threadIdx.x & 31) == 0) ws[threadIdx.x >> 5] = x;
    __syncthreads();
    if (threadIdx.x == 0) {
        int t = 0;
#pragma unroll
        for (int q = 0; q < 8; q++) t += ws[q];
        part[(isV ? 256 : 0) + b] = t;
    }
}

__global__ __launch_bounds__(256)
void scan_part2(int* __restrict__ part, int nbF, int nbV,
                int* __restrict__ totF, int* __restrict__ totV)
{
    const bool isV = blockIdx.x == 1;
    int* p = part + (isV ? 256 : 0);
    const int nb = isV ? nbV : nbF;
    int* total_out = isV ? totV : totF;
    const int t = threadIdx.x, lane = t & 31, w = t >> 5;
    const int x = (t < nb) ? p[t] : 0;
    int incl = x;
#pragma unroll
    for (int o = 1; o < 32; o <<= 1) {
        const int v = __shfl_up_sync(0xffffffffu, incl, o);
        if (lane >= o) incl += v;
    }
    __shared__ int ws[8], wex[8];
    if (lane == 31) ws[w] = incl;
    __syncthreads();
    if (t == 0) {
        int s = 0;
#pragma unroll
        for (int q = 0; q < 8; q++) { wex[q] = s; s += ws[q]; }
        total_out[0] = s;
    }
    __syncthreads();
    if (t < nb) p[t] = wex[w] + incl - x;
}

__global__ __launch_bounds__(256)
void scan_apply2(const int* __restrict__ cntF, int nF,
                 const int* __restrict__ cntV, int nV, int nbF,
                 const int* __restrict__ part,
                 int* __restrict__ offF, int* __restrict__ curF,
                 int* __restrict__ offV, int* __restrict__ curV)
{
    const bool isV = (int)blockIdx.x >= nbF;
    const int b = isV ? (blockIdx.x - nbF) : blockIdx.x;
    const int* cnt = isV ? cntV : cntF;
    const int n = isV ? nV : nF;
    int* off = isV ? offV : offF;
    int* cur = isV ? curV : curF;
    const int base = isV ? 256 : 0;
    const int i = b * 256 + threadIdx.x;
    const int t = threadIdx.x, lane = t & 31, w = t >> 5;
    const int x = (i < n) ? cnt[i] : 0;
    int incl = x;
#pragma unroll
    for (int o = 1; o < 32; o <<= 1) {
        const int v = __shfl_up_sync(0xffffffffu, incl, o);
        if (lane >= o) incl += v;
    }
    __shared__ int ws[8], wex[8];
    if (lane == 31) ws[w] = incl;
    __syncthreads();
    if (t == 0) {
        int s = 0;
#pragma unroll
        for (int q = 0; q < 8; q++) { wex[q] = s; s += ws[q]; }
    }
    __syncthreads();
    const int ex = part[base + b] + wex[w] + incl - x;
    if (i < n) { off[i] = ex; cur[i] = ex; }
}

__global__ __launch_bounds__(256)
void scatter_kernel(const int* __restrict__ src, const int* __restrict__ dst,
                    int* curF, int* curV, int* elF, int* elV)
{
    const int e = blockIdx.x * 256 + threadIdx.x;
    if (e >= EE) return;
    const int s = __ldg(&src[e]);
    const int d2 = __ldg(&dst[e]);
    elF[atomicAdd(&curF[d2], 1)] = s;
    elV[atomicAdd(&curV[s], 1)] = d2;
}

// ---------------- CSR gather-aggregate (half in, half out) -------------------
__global__ __launch_bounds__(256)
void aggregate(const __half* __restrict__ Hself, const __half* __restrict__ Hother,
               const int* __restrict__ off, const int* __restrict__ elist,
               __half* __restrict__ out, int n)
{
    const int row = blockIdx.x * 8 + threadIdx.y;
    if (row >= n) return;
    const int d = threadIdx.x * 8;
    const __half2* sp = reinterpret_cast<const __half2*>(&Hself[(size_t)row * D + d]);
    float2 s0 = __half22float2(sp[0]), s1 = __half22float2(sp[1]);
    float2 s2 = __half22float2(sp[2]), s3 = __half22float2(sp[3]);
    float a0x = 0.f, a0y = 0.f, a1x = 0.f, a1y = 0.f;
    float a2x = 0.f, a2y = 0.f, a3x = 0.f, a3y = 0.f;
    int j = __ldg(&off[row]);
    const int e = __ldg(&off[row + 1]);
    for (; j < e; j++) {
        const int o = __ldg(&elist[j]);
        const __half2* op = reinterpret_cast<const __half2*>(&Hother[(size_t)o * D + d]);
        const float2 v0 = __half22float2(op[0]), v1 = __half22float2(op[1]);
        const float2 v2 = __half22float2(op[2]), v3 = __half22float2(op[3]);
        a0x += fmaxf(s0.x + v0.x, 0.f); a0y += fmaxf(s0.y + v0.y, 0.f);
        a1x += fmaxf(s1.x + v1.x, 0.f); a1y += fmaxf(s1.y + v1.y, 0.f);
        a2x += fmaxf(s2.x + v2.x, 0.f); a2y += fmaxf(s2.y + v2.y, 0.f);
        a3x += fmaxf(s3.x + v3.x, 0.f); a3y += fmaxf(s3.y + v3.y, 0.f);
    }
    __half2* op2 = reinterpret_cast<__half2*>(&out[(size_t)row * D + d]);
    op2[0] = __floats2half2_rn(a0x, a0y);
    op2[1] = __floats2half2_rn(a1x, a1y);
    op2[2] = __floats2half2_rn(a2x, a2y);
    op2[3] = __floats2half2_rn(a3x, a3y);
}

// ---------------- attention pooling -----------------------------------------
__global__ __launch_bounds__(256)
void gate_kernel(const __half* __restrict__ F, const float* __restrict__ gW,
                 const float* __restrict__ gb, float* __restrict__ gate)
{
    const int w = threadIdx.x >> 5, lane = threadIdx.x & 31;
    const int row = blockIdx.x * 8 + w;
    if (row >= NF) return;
    float s = 0.f;
#pragma unroll
    for (int i = 0; i < 8; i++) {
        const int k = lane + i * 32;
        s += __half2float(F[(size_t)row * D + k]) * __ldg(&gW[k]);
    }
#pragma unroll
    for (int o = 16; o > 0; o >>= 1) s += __shfl_xor_sync(0xffffffff, s, o);
    if (lane == 0) gate[row] = s + gb[0];
}

__device__ __forceinline__ int lbound(const int* __restrict__ a, int n, int v)
{
    int lo = 0, hi = n;
    while (lo < hi) {
        const int mid = (lo + hi) >> 1;
        if (a[mid] < v) lo = mid + 1; else hi = mid;
    }
    return lo;
}

__global__ __launch_bounds__(256)
void graph_agg(const float* __restrict__ gate, const __half* __restrict__ T,
               const int* __restrict__ batch, float* __restrict__ gagg)
{
    __shared__ float red[256];
    __shared__ int sse[2];
    const int g = blockIdx.x, tid = threadIdx.x;
    if (tid == 0) sse[0] = lbound(batch, NF, g);
    if (tid == 1) sse[1] = lbound(batch, NF, g + 1);
    __syncthreads();
    const int s = sse[0], e = sse[1];

    float m = -INFINITY;
    for (int i = s + tid; i < e; i += 256) m = fmaxf(m, __ldg(&gate[i]));
    red[tid] = m; __syncthreads();
    for (int o = 128; o > 0; o >>= 1) {
        if (tid < o) red[tid] = fmaxf(red[tid], red[tid + o]);
        __syncthreads();
    }
    const float mm = red[0]; __syncthreads();

    float sum = 0.f;
    for (int i = s + tid; i < e; i += 256) sum += expf(__ldg(&gate[i]) - mm);
    red[tid] = sum; __syncthreads();
    for (int o = 128; o > 0; o >>= 1) {
        if (tid < o) red[tid] += red[tid + o];
        __syncthreads();
    }
    const float inv = (e > s) ? 1.f / red[0] : 0.f;

    float acc = 0.f;
    for (int i = s; i < e; i++) {
        const float alpha = expf(__ldg(&gate[i]) - mm) * inv;
        acc += alpha * __half2float(T[(size_t)i * D + tid]);
    }
    gagg[g * D + tid] = acc;
}

__global__ __launch_bounds__(256)
void final_g(const float* __restrict__ gagg, const float* __restrict__ glW,
             const float* __restrict__ glb, float* __restrict__ out)
{
    __shared__ float row[D];
    const int g = blockIdx.x, c = threadIdx.x;
    row[c] = gagg[g * D + c];
    __syncthreads();
    float s = glb[c];
#pragma unroll 8
    for (int k = 0; k < D; k++) s += row[k] * glW[(size_t)k * D + c];
    out[(size_t)g * D + c] = fmaxf(s, 0.f);
}

// ---------------------------------------------------------------------------
extern "C" void kernel_launch(void* const* d_in, const int* in_sizes, int n_in,
                              void* d_out, int out_size)
{
    const float* variables = (const float*)d_in[0];
    const float* factors   = (const float*)d_in[1];
    // d_in[2] = edge_attr (unused by the math)
    const int* edge_index  = (const int*)d_in[3];
    const int* batch       = (const int*)d_in[4];
    const float* mW_v2f = (const float*)d_in[5];
    const float* mb_v2f = (const float*)d_in[6];
    const float* cW_v2f = (const float*)d_in[7];
    const float* cb_v2f = (const float*)d_in[8];
    const float* mW_f2v = (const float*)d_in[9];
    const float* mb_f2v = (const float*)d_in[10];
    const float* cW_f2v = (const float*)d_in[11];
    const float* cb_f2v = (const float*)d_in[12];
    const float* gate_W = (const float*)d_in[13];
    const float* gate_b = (const float*)d_in[14];
    const float* att_W  = (const float*)d_in[15];
    const float* att_b  = (const float*)d_in[16];
    const float* gl_W   = (const float*)d_in[17];
    const float* gl_b   = (const float*)d_in[18];

    const int* src = edge_index;        // row 0: variable idx
    const int* dst = edge_index + EE;   // row 1: factor idx

    float* outV = (float*)d_out;
    float* outF = outV + (size_t)NV * D;
    float* outG = outF + (size_t)NF * D;

    __half *hFa, *hFb, *hFh, *hFagg, *hVa, *hVb, *hVh, *hVagg, *hW;
    float *gate, *gagg;
    int *cntF, *cntV, *offF, *offV, *curF, *curV, *elF, *elV, *part;
    cudaGetSymbolAddress((void**)&hFa, g_hFa);
    cudaGetSymbolAddress((void**)&hFb, g_hFb);
    cudaGetSymbolAddress((void**)&hFh, g_hFh);
    cudaGetSymbolAddress((void**)&hFagg, g_hFagg);
    cudaGetSymbolAddress((void**)&hVa, g_hVa);
    cudaGetSymbolAddress((void**)&hVb, g_hVb);
    cudaGetSymbolAddress((void**)&hVh, g_hVh);
    cudaGetSymbolAddress((void**)&hVagg, g_hVagg);
    cudaGetSymbolAddress((void**)&hW,  g_hW);
    cudaGetSymbolAddress((void**)&gate, g_gate);
    cudaGetSymbolAddress((void**)&gagg, g_gagg);
    cudaGetSymbolAddress((void**)&part, g_part);
    cudaGetSymbolAddress((void**)&cntF, g_cntF);
    cudaGetSymbolAddress((void**)&cntV, g_cntV);
    cudaGetSymbolAddress((void**)&offF, g_offF);
    cudaGetSymbolAddress((void**)&offV, g_offV);
    cudaGetSymbolAddress((void**)&curF, g_curF);
    cudaGetSymbolAddress((void**)&curV, g_curV);
    cudaGetSymbolAddress((void**)&elF,  g_elF);
    cudaGetSymbolAddress((void**)&elV,  g_elV);

    __half* wm_v2f = hW;
    __half* wc_v2f = hW + 262144;
    __half* wm_f2v = hW + 524288;
    __half* wc_f2v = hW + 786432;
    __half* watt   = hW + 1048576;

    cudaFuncSetAttribute(gemm_single<EP_BIAS, 256, false>,           cudaFuncAttributeMaxDynamicSharedMemorySize, SMEM_BYTES);
    cudaFuncSetAttribute(gemm_single<EP_NONE, 256, false>,           cudaFuncAttributeMaxDynamicSharedMemorySize, SMEM_BYTES);
    cudaFuncSetAttribute(gemm_single<EP_RELU_BIAS, 512, false>,      cudaFuncAttributeMaxDynamicSharedMemorySize, SMEM_BYTES);
    cudaFuncSetAttribute(gemm_single<EP_RELU_BIAS, 512, true>,       cudaFuncAttributeMaxDynamicSharedMemorySize, SMEM_BYTES);
    cudaFuncSetAttribute(gemm_single<EP_RELU_BIAS_RES, 512, false>,  cudaFuncAttributeMaxDynamicSharedMemorySize, SMEM_BYTES);
    cudaFuncSetAttribute(gemm_single<EP_RELU_BIAS_RES, 512, true>,   cudaFuncAttributeMaxDynamicSharedMemorySize, SMEM_BYTES);
    cudaFuncSetAttribute(gemm_dual<EP_BIAS, EP_NONE>,                cudaFuncAttributeMaxDynamicSharedMemorySize, SMEM_BYTES);

    // side stream + events (host-side objects only; created once, reused —
    // the launched work is identical on every call)
    static cudaStream_t s2 = nullptr;
    static cudaEvent_t evFork = nullptr, evJoin = nullptr;
    static cudaEvent_t evFork2 = nullptr, evJoin2 = nullptr;
    if (s2 == nullptr) {
        cudaStreamCreateWithFlags(&s2, cudaStreamNonBlocking);
        cudaEventCreateWithFlags(&evFork,  cudaEventDisableTiming);
        cudaEventCreateWithFlags(&evJoin,  cudaEventDisableTiming);
        cudaEventCreateWithFlags(&evFork2, cudaEventDisableTiming);
        cudaEventCreateWithFlags(&evJoin2, cudaEventDisableTiming);
    }

    // ---- fork: CSR build chain on side stream (independent of convert/GEMM) --
    cudaEventRecord(evFork, 0);
    cudaStreamWaitEvent(s2, evFork, 0);
    cudaMemsetAsync(cntF, 0, NF * sizeof(int), s2);
    cudaMemsetAsync(cntV, 0, NV * sizeof(int), s2);
    const int eb = (EE + 255) / 256;
    hist_kernel<<<eb, 256, 0, s2>>>(src, dst, cntF, cntV);
    const int nbF = (NF + 255) / 256, nbV = (NV + 255) / 256;   // 157, 79
    blk_sum2<<<nbF + nbV, 256, 0, s2>>>(cntF, NF, cntV, NV, nbF, part);
    scan_part2<<<2, 256, 0, s2>>>(part, nbF, nbV, offF + NF, offV + NV);
    scan_apply2<<<nbF + nbV, 256, 0, s2>>>(cntF, NF, cntV, NV, nbF, part,
                                           offF, curF, offV, curV);
    scatter_kernel<<<eb, 256, 0, s2>>>(src, dst, curF, curV, elF, elV);
    cudaEventRecord(evJoin, s2);

    // ---- main stream: convert inputs + weights to half ----
    {
        CvtArgs a;
        a.src[0] = variables; a.dst[0] = hVa;
        a.src[1] = factors;   a.dst[1] = hFa;
        a.src[2] = mW_v2f;    a.dst[2] = wm_v2f;
        a.src[3] = cW_v2f;    a.dst[3] = wc_v2f;
        a.src[4] = mW_f2v;    a.dst[4] = wm_f2v;
        a.src[5] = cW_f2v;    a.dst[5] = wc_f2v;
        a.src[6] = att_W;     a.dst[6] = watt;
        const int sz[7] = {NV * D, NF * D, 262144, 262144, 262144, 262144, 65536};
        a.off[0] = 0;
        for (int i = 0; i < 7; i++) a.off[i + 1] = a.off[i] + sz[i];
        convert_multi<<<(a.off[7] + 255) / 256, 256>>>(a);
    }

    const dim3 blk(256);
    const int nYF = (NF + 127) / 128;   // 313
    const int nYV = (NV + 127) / 128;   // 157
    const dim3 gridF(2, nYF);
    const dim3 gridV(2, nYV);
    const dim3 gridDual(2, nYF + nYV);
    const dim3 aggBlk(32, 8);

    __half* Fcur = hFa;  __half* Vcur = hVa;
    __half* Fnxt = hFb;  __half* Vnxt = hVb;

    bool joined = false;
    for (int l = 0; l < 2; l++) {
        // ---- variable -> factor ----
        {
            const __half* mW = wm_v2f + (size_t)l * D2 * D;
            const float* mb = mb_v2f + (size_t)l * D;
            const __half* cW = wc_v2f + (size_t)l * D2 * D;
            const float* cb = cb_v2f + (size_t)l * D;

            gemm_dual<EP_BIAS, EP_NONE><<<gridDual, blk, SMEM_BYTES>>>(
                Fcur, mW, hFh, mb, NF, nYF,
                Vcur, mW + D * D, hVh, NV);
            if (!joined) {  // CSR ready required from the first aggregate on
                cudaStreamWaitEvent(0, evJoin, 0);
                joined = true;
            }
            aggregate<<<(NF + 7) / 8, aggBlk>>>(hFh, hVh, offF, elF, hFagg, NF);
            if (l == 0)
                gemm_single<EP_RELU_BIAS, 512, false><<<gridF, blk, SMEM_BYTES>>>(
                    Fcur, hFagg, cW, Fnxt, cb, nullptr, nullptr, NF);
            else
                gemm_single<EP_RELU_BIAS, 512, true><<<gridF, blk, SMEM_BYTES>>>(
                    Fcur, hFagg, cW, Fnxt, cb, nullptr, outF, NF);
            __half* t = Fcur; Fcur = Fnxt; Fnxt = t;
        }
        // ---- factor -> variable ----
        {
            const __half* mW = wm_f2v + (size_t)l * D2 * D;
            const float* mb = mb_f2v + (size_t)l * D;
            const __half* cW = wc_f2v + (size_t)l * D2 * D;
            const float* cb = cb_f2v + (size_t)l * D;

            gemm_dual<EP_BIAS, EP_NONE><<<gridDual, blk, SMEM_BYTES>>>(
                Vcur, mW, hVh, mb, NV, nYV,
                Fcur, mW + D * D, hFh, NF);
            aggregate<<<(NV + 7) / 8, aggBlk>>>(hVh, hFh, offV, elV, hVagg, NV);
            if (l == 0)
                gemm_single<EP_RELU_BIAS_RES, 512, false><<<gridV, blk, SMEM_BYTES>>>(
                    Vcur, hVagg, cW, Vnxt, cb, Vcur, nullptr, NV);
            else
                gemm_single<EP_RELU_BIAS_RES, 512, true><<<gridV, blk, SMEM_BYTES>>>(
                    Vcur, hVagg, cW, Vnxt, cb, Vcur, outV, NV);
            __half* t = Vcur; Vcur = Vnxt; Vnxt = t;
        }
    }
    // after 2 layers: Fcur == hFa (== F2, also in outF), Vcur == hVa (in outV)

    // ---- GlobalNode attention pooling (gate forked beside the att GEMM) ----
    cudaEventRecord(evFork2, 0);
    cudaStreamWaitEvent(s2, evFork2, 0);
    gate_kernel<<<(NF + 7) / 8, 256, 0, s2>>>(Fcur, gate_W, gate_b, gate);
    cudaEventRecord(evJoin2, s2);
    gemm_single<EP_BIAS, 256, false><<<gridF, blk, SMEM_BYTES>>>(
        Fcur, nullptr, watt, hFh, att_b, nullptr, nullptr, NF);
    cudaStreamWaitEvent(0, evJoin2, 0);
    graph_agg<<<GG, 256>>>(gate, hFh, batch, gagg);
    final_g<<<GG, 256>>>(gagg, gl_W, gl_b, outG);
}

// round 16
// speedup vs baseline: 1.3556x; 1.0006x over previous
#include <cuda_runtime.h>
#include <cuda_fp16.h>
#include <math.h>
#include <stdint.h>

#define NV 20000
#define NF 40000
#define EE 320000
#define GG 64
#define D  256
#define D2 512

// ---------------- scratch (device globals; no allocation allowed) ----------
__device__ __half g_hFa[NF * D], g_hFb[NF * D], g_hFh[NF * D], g_hFagg[NF * D];
__device__ __half g_hVa[NV * D], g_hVb[NV * D], g_hVh[NV * D], g_hVagg[NV * D];
__device__ __half g_hVh2[NV * D];     // side-stream f2v top half-product
__device__ __half g_hW[1114112];
__device__ float g_gate[NF];
__device__ float g_gagg[GG * D];
__device__ int   g_part[512];
// CSR scratch
__device__ int g_cntF[NF], g_cntV[NV];
__device__ int g_offF[NF + 1], g_offV[NV + 1];
__device__ int g_curF[NF], g_curV[NV];
__device__ int g_elF[EE], g_elV[EE];

enum { EP_NONE = 0, EP_BIAS = 1, EP_RELU_BIAS = 2, EP_RELU_BIAS_RES = 3 };

__device__ __forceinline__ uint32_t smem_u32(const void* p) {
    uint32_t a;
    asm("{ .reg .u64 t; cvta.to.shared.u64 t, %1; cvt.u32.u64 %0, t; }"
        : "=r"(a) : "l"(p));
    return a;
}
__device__ __forceinline__ void ldm_x4(unsigned& r0, unsigned& r1,
                                       unsigned& r2, unsigned& r3, uint32_t a) {
    asm volatile("ldmatrix.sync.aligned.m8n8.x4.shared.b16 {%0,%1,%2,%3}, [%4];"
                 : "=r"(r0), "=r"(r1), "=r"(r2), "=r"(r3) : "r"(a));
}
__device__ __forceinline__ void ldm_x4_t(unsigned& r0, unsigned& r1,
                                         unsigned& r2, unsigned& r3, uint32_t a) {
    asm volatile("ldmatrix.sync.aligned.m8n8.x4.trans.shared.b16 {%0,%1,%2,%3}, [%4];"
                 : "=r"(r0), "=r"(r1), "=r"(r2), "=r"(r3) : "r"(a));
}
__device__ __forceinline__ void mma_f16(float* d, const unsigned* a,
                                        const unsigned* b, const float* c) {
    asm volatile(
        "mma.sync.aligned.m16n8k16.row.col.f32.f16.f16.f32 "
        "{%0,%1,%2,%3}, {%4,%5,%6,%7}, {%8,%9}, {%10,%11,%12,%13};"
        : "=f"(d[0]), "=f"(d[1]), "=f"(d[2]), "=f"(d[3])
        : "r"(a[0]), "r"(a[1]), "r"(a[2]), "r"(a[3]),
          "r"(b[0]), "r"(b[1]),
          "f"(c[0]), "f"(c[1]), "f"(c[2]), "f"(c[3]));
}

#define ASH 5120
#define BSH 4352
#define BS_BASE 40960
#define SMEM_BYTES 75776

// ---- GEMM body: C[128x128 tile] = concat-A[M x KTOT] @ W[KTOT x 256] ------
template <int MODE, int KTOT, bool F32OUT>
__device__ __forceinline__ void gemm_body(
    char* smem,
    const __half* __restrict__ A0, const __half* __restrict__ A1,
    const __half* __restrict__ W, __half* __restrict__ Cout,
    const float* __restrict__ bias, const __half* __restrict__ res,
    float* __restrict__ Cout32,
    int M, int yBlk, int xBlk)
{
    __half* AsB = reinterpret_cast<__half*>(smem);
    __half* BsB = reinterpret_cast<__half*>(smem + BS_BASE);

    const int tid  = threadIdx.x;
    const int wid  = tid >> 5;
    const int lane = tid & 31;
    const int g = lane >> 2;
    const int c = lane & 3;
    const int rowBase = yBlk * 128;
    const int colBase = xBlk * 128;
    const int wr = (wid & 1) * 64;
    const int wc = (wid >> 1) * 32;

    float acc[4][4][4];
#pragma unroll
    for (int i = 0; i < 4; i++)
#pragma unroll
        for (int j = 0; j < 4; j++)
#pragma unroll
            for (int k = 0; k < 4; k++) acc[i][j][k] = 0.f;

    auto issue = [&](int slab) {
        const __half* Asrc = (KTOT == 512 && slab >= 8) ? A1 : A0;
        const int kb = (slab * 32) & 255;
        __half* As = AsB + (slab & 3) * ASH;
        __half* Bs = BsB + (slab & 3) * BSH;
#pragma unroll
        for (int it = 0; it < 2; it++) {
            const int id = it * 256 + tid;
            const int r = id >> 2, kq = id & 3;
            const int gr = rowBase + r;
            const int grc = (gr < M) ? gr : (M - 1);
            const __half* src = &Asrc[(size_t)grc * D + kb + kq * 8];
            const uint32_t dst = smem_u32(As + r * 40 + kq * 8);
            const int sz = (gr < M) ? 16 : 0;
            asm volatile("cp.async.cg.shared.global [%0], [%1], 16, %2;\n"
                         :: "r"(dst), "l"(src), "r"(sz) : "memory");
        }
#pragma unroll
        for (int it = 0; it < 2; it++) {
            const int id = it * 256 + tid;
            const int kk = id >> 4, n8 = (id & 15) * 8;
            const __half* src = &W[(size_t)(slab * 32 + kk) * D + colBase + n8];
            const uint32_t dst = smem_u32(Bs + kk * 136 + n8);
            asm volatile("cp.async.cg.shared.global [%0], [%1], 16;\n"
                         :: "r"(dst), "l"(src) : "memory");
        }
        asm volatile("cp.async.commit_group;\n" ::: "memory");
    };

    constexpr int NSLAB = KTOT / 32;
    issue(0); issue(1); issue(2);

    for (int s = 0; s < NSLAB; s++) {
        asm volatile("cp.async.wait_group 2;\n" ::: "memory");
        __syncthreads();
        if (s + 3 < NSLAB) issue(s + 3);

        const uint32_t aBase = smem_u32(AsB + (s & 3) * ASH);
        const uint32_t bBase = smem_u32(BsB + (s & 3) * BSH);
#pragma unroll
        for (int ks = 0; ks < 32; ks += 16) {
            unsigned a[4][4], b[4][2];
#pragma unroll
            for (int mf = 0; mf < 4; mf++) {
                const uint32_t addr = aBase +
                    (((wr + mf * 16 + (lane & 15)) * 40 + ks + (lane >> 4) * 8) << 1);
                ldm_x4(a[mf][0], a[mf][1], a[mf][2], a[mf][3], addr);
            }
#pragma unroll
            for (int p = 0; p < 2; p++) {
                const uint32_t addr = bBase +
                    ((((ks + (lane & 7) + ((lane >> 3) & 1) * 8)) * 136 +
                      wc + p * 16 + (lane >> 4) * 8) << 1);
                ldm_x4_t(b[2 * p][0], b[2 * p][1], b[2 * p + 1][0], b[2 * p + 1][1], addr);
            }
#pragma unroll
            for (int mf = 0; mf < 4; mf++)
#pragma unroll
                for (int nf = 0; nf < 4; nf++)
                    mma_f16(acc[mf][nf], a[mf], b[nf], acc[mf][nf]);
        }
    }

#pragma unroll
    for (int mf = 0; mf < 4; mf++) {
#pragma unroll
        for (int half = 0; half < 2; half++) {
            const int r = rowBase + wr + mf * 16 + g + half * 8;
            if (r >= M) continue;
#pragma unroll
            for (int nf = 0; nf < 4; nf++) {
                const int col = colBase + wc + nf * 8 + 2 * c;
                float2 v = make_float2(acc[mf][nf][half * 2], acc[mf][nf][half * 2 + 1]);
                if (MODE == EP_BIAS) {
                    v.x += bias[col + 0];
                    v.y += bias[col + 1];
                } else if (MODE == EP_RELU_BIAS || MODE == EP_RELU_BIAS_RES) {
                    v.x = fmaxf(v.x + bias[col + 0], 0.f);
                    v.y = fmaxf(v.y + bias[col + 1], 0.f);
                    if (MODE == EP_RELU_BIAS_RES) {
                        const __half2 rr = *reinterpret_cast<const __half2*>(&res[(size_t)r * D + col]);
                        const float2 rf = __half22float2(rr);
                        v.x += rf.x; v.y += rf.y;
                    }
                }
                *reinterpret_cast<__half2*>(&Cout[(size_t)r * D + col]) =
                    __floats2half2_rn(v.x, v.y);
                if (F32OUT) {
                    const float2 hf = __half22float2(__floats2half2_rn(v.x, v.y));
                    *reinterpret_cast<float2*>(&Cout32[(size_t)r * D + col]) = hf;
                }
            }
        }
    }
}

template <int MODE, int KTOT, bool F32OUT>
__global__ __launch_bounds__(256, 2)
void gemm_single(const __half* __restrict__ A0, const __half* __restrict__ A1,
                 const __half* __restrict__ W, __half* __restrict__ Cout,
                 const float* __restrict__ bias, const __half* __restrict__ res,
                 float* __restrict__ Cout32, int M)
{
    extern __shared__ char smem[];
    gemm_body<MODE, KTOT, F32OUT>(smem, A0, A1, W, Cout, bias, res, Cout32, M,
                                  blockIdx.y, blockIdx.x);
}

template <int MODEA, int MODEB>
__global__ __launch_bounds__(256, 2)
void gemm_dual(const __half* __restrict__ Aa, const __half* __restrict__ Wa,
               __half* __restrict__ Ca, const float* __restrict__ biasa,
               int Ma, int nYa,
               const __half* __restrict__ Ab, const __half* __restrict__ Wb,
               __half* __restrict__ Cb, int Mb)
{
    extern __shared__ char smem[];
    if ((int)blockIdx.y < nYa)
        gemm_body<MODEA, 256, false>(smem, Aa, nullptr, Wa, Ca, biasa, nullptr,
                                     nullptr, Ma, blockIdx.y, blockIdx.x);
    else
        gemm_body<MODEB, 256, false>(smem, Ab, nullptr, Wb, Cb, nullptr, nullptr,
                                     nullptr, Mb, blockIdx.y - nYa, blockIdx.x);
}

// ---------------- batched fp32 -> fp16 convert -------------------------------
struct CvtArgs {
    const float* src[7];
    __half* dst[7];
    int off[8];
};
__global__ __launch_bounds__(256)
void convert_multi(CvtArgs a)
{
    const int i = blockIdx.x * 256 + threadIdx.x;
    if (i >= a.off[7]) return;
    int s = 0;
    while (i >= a.off[s + 1]) s++;
    const int j = i - a.off[s];
    a.dst[s][j] = __float2half_rn(__ldg(&a.src[s][j]));
}

// ---------------- CSR build --------------------------------------------------
__global__ __launch_bounds__(256)
void hist_kernel(const int* __restrict__ src, const int* __restrict__ dst,
                 int* cntF, int* cntV)
{
    const int e = blockIdx.x * 256 + threadIdx.x;
    if (e >= EE) return;
    atomicAdd(&cntF[__ldg(&dst[e])], 1);
    atomicAdd(&cntV[__ldg(&src[e])], 1);
}

__global__ __launch_bounds__(256)
void blk_sum2(const int* __restrict__ cntF, int nF, const int* __restrict__ cntV,
              int nV, int nbF, int* __restrict__ part)
{
    const bool isV = (int)blockIdx.x >= nbF;
    const int b = isV ? (blockIdx.x - nbF) : blockIdx.x;
    const int* cnt = isV ? cntV : cntF;
    const int n = isV ? nV : nF;
    const int i = b * 256 + threadIdx.x;
    int x = (i < n) ? cnt[i] : 0;
#pragma unroll
    for (int o = 16; o > 0; o >>= 1) x += __shfl_xor_sync(0xffffffffu, x, o);
    __shared__ int ws[8];
    if ((threadIdx.x & 31) == 0) ws[threadIdx.x >> 5] = x;
    __syncthreads();
    if (threadIdx.x == 0) {
        int t = 0;
#pragma unroll
        for (int q = 0; q < 8; q++) t += ws[q];
        part[(isV ? 256 : 0) + b] = t;
    }
}

__global__ __launch_bounds__(256)
void scan_part2(int* __restrict__ part, int nbF, int nbV,
                int* __restrict__ totF, int* __restrict__ totV)
{
    const bool isV = blockIdx.x == 1;
    int* p = part + (isV ? 256 : 0);
    const int nb = isV ? nbV : nbF;
    int* total_out = isV ? totV : totF;
    const int t = threadIdx.x, lane = t & 31, w = t >> 5;
    const int x = (t < nb) ? p[t] : 0;
    int incl = x;
#pragma unroll
    for (int o = 1; o < 32; o <<= 1) {
        const int v = __shfl_up_sync(0xffffffffu, incl, o);
        if (lane >= o) incl += v;
    }
    __shared__ int ws[8], wex[8];
    if (lane == 31) ws[w] = incl;
    __syncthreads();
    if (t == 0) {
        int s = 0;
#pragma unroll
        for (int q = 0; q < 8; q++) { wex[q] = s; s += ws[q]; }
        total_out[0] = s;
    }
    __syncthreads();
    if (t < nb) p[t] = wex[w] + incl - x;
}

__global__ __launch_bounds__(256)
void scan_apply2(const int* __restrict__ cntF, int nF,
                 const int* __restrict__ cntV, int nV, int nbF,
                 const int* __restrict__ part,
                 int* __restrict__ offF, int* __restrict__ curF,
                 int* __restrict__ offV, int* __restrict__ curV)
{
    const bool isV = (int)blockIdx.x >= nbF;
    const int b = isV ? (blockIdx.x - nbF) : blockIdx.x;
    const int* cnt = isV ? cntV : cntF;
    const int n = isV ? nV : nF;
    int* off = isV ? offV : offF;
    int* cur = isV ? curV : curF;
    const int base = isV ? 256 : 0;
    const int i = b * 256 + threadIdx.x;
    const int t = threadIdx.x, lane = t & 31, w = t >> 5;
    const int x = (i < n) ? cnt[i] : 0;
    int incl = x;
#pragma unroll
    for (int o = 1; o < 32; o <<= 1) {
        const int v = __shfl_up_sync(0xffffffffu, incl, o);
        if (lane >= o) incl += v;
    }
    __shared__ int ws[8], wex[8];
    if (lane == 31) ws[w] = incl;
    __syncthreads();
    if (t == 0) {
        int s = 0;
#pragma unroll
        for (int q = 0; q < 8; q++) { wex[q] = s; s += ws[q]; }
    }
    __syncthreads();
    const int ex = part[base + b] + wex[w] + incl - x;
    if (i < n) { off[i] = ex; cur[i] = ex; }
}

__global__ __launch_bounds__(256)
void scatter_kernel(const int* __restrict__ src, const int* __restrict__ dst,
                    int* curF, int* curV, int* elF, int* elV)
{
    const int e = blockIdx.x * 256 + threadIdx.x;
    if (e >= EE) return;
    const int s = __ldg(&src[e]);
    const int d2 = __ldg(&dst[e]);
    elF[atomicAdd(&curF[d2], 1)] = s;
    elV[atomicAdd(&curV[s], 1)] = d2;
}

// ---------------- CSR gather-aggregate (half in, half out) -------------------
__global__ __launch_bounds__(256)
void aggregate(const __half* __restrict__ Hself, const __half* __restrict__ Hother,
               const int* __restrict__ off, const int* __restrict__ elist,
               __half* __restrict__ out, int n)
{
    const int row = blockIdx.x * 8 + threadIdx.y;
    if (row >= n) return;
    const int d = threadIdx.x * 8;
    const __half2* sp = reinterpret_cast<const __half2*>(&Hself[(size_t)row * D + d]);
    float2 s0 = __half22float2(sp[0]), s1 = __half22float2(sp[1]);
    float2 s2 = __half22float2(sp[2]), s3 = __half22float2(sp[3]);
    float a0x = 0.f, a0y = 0.f, a1x = 0.f, a1y = 0.f;
    float a2x = 0.f, a2y = 0.f, a3x = 0.f, a3y = 0.f;
    int j = __ldg(&off[row]);
    const int e = __ldg(&off[row + 1]);
    for (; j < e; j++) {
        const int o = __ldg(&elist[j]);
        const __half2* op = reinterpret_cast<const __half2*>(&Hother[(size_t)o * D + d]);
        const float2 v0 = __half22float2(op[0]), v1 = __half22float2(op[1]);
        const float2 v2 = __half22float2(op[2]), v3 = __half22float2(op[3]);
        a0x += fmaxf(s0.x + v0.x, 0.f); a0y += fmaxf(s0.y + v0.y, 0.f);
        a1x += fmaxf(s1.x + v1.x, 0.f); a1y += fmaxf(s1.y + v1.y, 0.f);
        a2x += fmaxf(s2.x + v2.x, 0.f); a2y += fmaxf(s2.y + v2.y, 0.f);
        a3x += fmaxf(s3.x + v3.x, 0.f); a3y += fmaxf(s3.y + v3.y, 0.f);
    }
    __half2* op2 = reinterpret_cast<__half2*>(&out[(size_t)row * D + d]);
    op2[0] = __floats2half2_rn(a0x, a0y);
    op2[1] = __floats2half2_rn(a1x, a1y);
    op2[2] = __floats2half2_rn(a2x, a2y);
    op2[3] = __floats2half2_rn(a3x, a3y);
}

// ---------------- attention pooling -----------------------------------------
__global__ __launch_bounds__(256)
void gate_kernel(const __half* __restrict__ F, const float* __restrict__ gW,
                 const float* __restrict__ gb, float* __restrict__ gate)
{
    const int w = threadIdx.x >> 5, lane = threadIdx.x & 31;
    const int row = blockIdx.x * 8 + w;
    if (row >= NF) return;
    float s = 0.f;
#pragma unroll
    for (int i = 0; i < 8; i++) {
        const int k = lane + i * 32;
        s += __half2float(F[(size_t)row * D + k]) * __ldg(&gW[k]);
    }
#pragma unroll
    for (int o = 16; o > 0; o >>= 1) s += __shfl_xor_sync(0xffffffff, s, o);
    if (lane == 0) gate[row] = s + gb[0];
}

__device__ __forceinline__ int lbound(const int* __restrict__ a, int n, int v)
{
    int lo = 0, hi = n;
    while (lo < hi) {
        const int mid = (lo + hi) >> 1;
        if (a[mid] < v) lo = mid + 1; else hi = mid;
    }
    return lo;
}

__global__ __launch_bounds__(256)
void graph_agg(const float* __restrict__ gate, const __half* __restrict__ T,
               const int* __restrict__ batch, float* __restrict__ gagg)
{
    __shared__ float red[256];
    __shared__ int sse[2];
    const int g = blockIdx.x, tid = threadIdx.x;
    if (tid == 0) sse[0] = lbound(batch, NF, g);
    if (tid == 1) sse[1] = lbound(batch, NF, g + 1);
    __syncthreads();
    const int s = sse[0], e = sse[1];

    float m = -INFINITY;
    for (int i = s + tid; i < e; i += 256) m = fmaxf(m, __ldg(&gate[i]));
    red[tid] = m; __syncthreads();
    for (int o = 128; o > 0; o >>= 1) {
        if (tid < o) red[tid] = fmaxf(red[tid], red[tid + o]);
        __syncthreads();
    }
    const float mm = red[0]; __syncthreads();

    float sum = 0.f;
    for (int i = s + tid; i < e; i += 256) sum += expf(__ldg(&gate[i]) - mm);
    red[tid] = sum; __syncthreads();
    for (int o = 128; o > 0; o >>= 1) {
        if (tid < o) red[tid] += red[tid + o];
        __syncthreads();
    }
    const float inv = (e > s) ? 1.f / red[0] : 0.f;

    float acc = 0.f;
    for (int i = s; i < e; i++) {
        const float alpha = expf(__ldg(&gate[i]) - mm) * inv;
        acc += alpha * __half2float(T[(size_t)i * D + tid]);
    }
    gagg[g * D + tid] = acc;
}

__global__ __launch_bounds__(256)
void final_g(const float* __restrict__ gagg, const float* __restrict__ glW,
             const float* __restrict__ glb, float* __restrict__ out)
{
    __shared__ float row[D];
    const int g = blockIdx.x, c = threadIdx.x;
    row[c] = gagg[g * D + c];
    __syncthreads();
    float s = glb[c];
#pragma unroll 8
    for (int k = 0; k < D; k++) s += row[k] * glW[(size_t)k * D + c];
    out[(size_t)g * D + c] = fmaxf(s, 0.f);
}

// ---------------------------------------------------------------------------
extern "C" void kernel_launch(void* const* d_in, const int* in_sizes, int n_in,
                              void* d_out, int out_size)
{
    const float* variables = (const float*)d_in[0];
    const float* factors   = (const float*)d_in[1];
    // d_in[2] = edge_attr (unused by the math)
    const int* edge_index  = (const int*)d_in[3];
    const int* batch       = (const int*)d_in[4];
    const float* mW_v2f = (const float*)d_in[5];
    const float* mb_v2f = (const float*)d_in[6];
    const float* cW_v2f = (const float*)d_in[7];
    const float* cb_v2f = (const float*)d_in[8];
    const float* mW_f2v = (const float*)d_in[9];
    const float* mb_f2v = (const float*)d_in[10];
    const float* cW_f2v = (const float*)d_in[11];
    const float* cb_f2v = (const float*)d_in[12];
    const float* gate_W = (const float*)d_in[13];
    const float* gate_b = (const float*)d_in[14];
    const float* att_W  = (const float*)d_in[15];
    const float* att_b  = (const float*)d_in[16];
    const float* gl_W   = (const float*)d_in[17];
    const float* gl_b   = (const float*)d_in[18];

    const int* src = edge_index;        // row 0: variable idx
    const int* dst = edge_index + EE;   // row 1: factor idx

    float* outV = (float*)d_out;
    float* outF = outV + (size_t)NV * D;
    float* outG = outF + (size_t)NF * D;

    __half *hFa, *hFb, *hFh, *hFagg, *hVa, *hVb, *hVh, *hVagg, *hVh2, *hW;
    float *gate, *gagg;
    int *cntF, *cntV, *offF, *offV, *curF, *curV, *elF, *elV, *part;
    cudaGetSymbolAddress((void**)&hFa, g_hFa);
    cudaGetSymbolAddress((void**)&hFb, g_hFb);
    cudaGetSymbolAddress((void**)&hFh, g_hFh);
    cudaGetSymbolAddress((void**)&hFagg, g_hFagg);
    cudaGetSymbolAddress((void**)&hVa, g_hVa);
    cudaGetSymbolAddress((void**)&hVb, g_hVb);
    cudaGetSymbolAddress((void**)&hVh, g_hVh);
    cudaGetSymbolAddress((void**)&hVagg, g_hVagg);
    cudaGetSymbolAddress((void**)&hVh2, g_hVh2);
    cudaGetSymbolAddress((void**)&hW,  g_hW);
    cudaGetSymbolAddress((void**)&gate, g_gate);
    cudaGetSymbolAddress((void**)&gagg, g_gagg);
    cudaGetSymbolAddress((void**)&part, g_part);
    cudaGetSymbolAddress((void**)&cntF, g_cntF);
    cudaGetSymbolAddress((void**)&cntV, g_cntV);
    cudaGetSymbolAddress((void**)&offF, g_offF);
    cudaGetSymbolAddress((void**)&offV, g_offV);
    cudaGetSymbolAddress((void**)&curF, g_curF);
    cudaGetSymbolAddress((void**)&curV, g_curV);
    cudaGetSymbolAddress((void**)&elF,  g_elF);
    cudaGetSymbolAddress((void**)&elV,  g_elV);

    __half* wm_v2f = hW;
    __half* wc_v2f = hW + 262144;
    __half* wm_f2v = hW + 524288;
    __half* wc_f2v = hW + 786432;
    __half* watt   = hW + 1048576;

    cudaFuncSetAttribute(gemm_single<EP_BIAS, 256, false>,           cudaFuncAttributeMaxDynamicSharedMemorySize, SMEM_BYTES);
    cudaFuncSetAttribute(gemm_single<EP_NONE, 256, false>,           cudaFuncAttributeMaxDynamicSharedMemorySize, SMEM_BYTES);
    cudaFuncSetAttribute(gemm_single<EP_RELU_BIAS, 512, false>,      cudaFuncAttributeMaxDynamicSharedMemorySize, SMEM_BYTES);
    cudaFuncSetAttribute(gemm_single<EP_RELU_BIAS, 512, true>,       cudaFuncAttributeMaxDynamicSharedMemorySize, SMEM_BYTES);
    cudaFuncSetAttribute(gemm_single<EP_RELU_BIAS_RES, 512, false>,  cudaFuncAttributeMaxDynamicSharedMemorySize, SMEM_BYTES);
    cudaFuncSetAttribute(gemm_single<EP_RELU_BIAS_RES, 512, true>,   cudaFuncAttributeMaxDynamicSharedMemorySize, SMEM_BYTES);
    cudaFuncSetAttribute(gemm_dual<EP_BIAS, EP_NONE>,                cudaFuncAttributeMaxDynamicSharedMemorySize, SMEM_BYTES);

    // side stream + events (host-side objects only; created once, reused)
    static cudaStream_t s2 = nullptr;
    static cudaEvent_t evFork = nullptr, evJoin = nullptr;
    static cudaEvent_t evFork2 = nullptr, evJoin2 = nullptr;
    static cudaEvent_t evLF[2] = {nullptr, nullptr};
    static cudaEvent_t evLJ[2] = {nullptr, nullptr};
    if (s2 == nullptr) {
        cudaStreamCreateWithFlags(&s2, cudaStreamNonBlocking);
        cudaEventCreateWithFlags(&evFork,  cudaEventDisableTiming);
        cudaEventCreateWithFlags(&evJoin,  cudaEventDisableTiming);
        cudaEventCreateWithFlags(&evFork2, cudaEventDisableTiming);
        cudaEventCreateWithFlags(&evJoin2, cudaEventDisableTiming);
        for (int i = 0; i < 2; i++) {
            cudaEventCreateWithFlags(&evLF[i], cudaEventDisableTiming);
            cudaEventCreateWithFlags(&evLJ[i], cudaEventDisableTiming);
        }
    }

    // ---- fork: CSR build chain on side stream ----
    cudaEventRecord(evFork, 0);
    cudaStreamWaitEvent(s2, evFork, 0);
    cudaMemsetAsync(cntF, 0, NF * sizeof(int), s2);
    cudaMemsetAsync(cntV, 0, NV * sizeof(int), s2);
    const int eb = (EE + 255) / 256;
    hist_kernel<<<eb, 256, 0, s2>>>(src, dst, cntF, cntV);
    const int nbF = (NF + 255) / 256, nbV = (NV + 255) / 256;
    blk_sum2<<<nbF + nbV, 256, 0, s2>>>(cntF, NF, cntV, NV, nbF, part);
    scan_part2<<<2, 256, 0, s2>>>(part, nbF, nbV, offF + NF, offV + NV);
    scan_apply2<<<nbF + nbV, 256, 0, s2>>>(cntF, NF, cntV, NV, nbF, part,
                                           offF, curF, offV, curV);
    scatter_kernel<<<eb, 256, 0, s2>>>(src, dst, curF, curV, elF, elV);
    cudaEventRecord(evJoin, s2);

    // ---- main stream: convert inputs + weights to half ----
    {
        CvtArgs a;
        a.src[0] = variables; a.dst[0] = hVa;
        a.src[1] = factors;   a.dst[1] = hFa;
        a.src[2] = mW_v2f;    a.dst[2] = wm_v2f;
        a.src[3] = cW_v2f;    a.dst[3] = wc_v2f;
        a.src[4] = mW_f2v;    a.dst[4] = wm_f2v;
        a.src[5] = cW_f2v;    a.dst[5] = wc_f2v;
        a.src[6] = att_W;     a.dst[6] = watt;
        const int sz[7] = {NV * D, NF * D, 262144, 262144, 262144, 262144, 65536};
        a.off[0] = 0;
        for (int i = 0; i < 7; i++) a.off[i + 1] = a.off[i] + sz[i];
        convert_multi<<<(a.off[7] + 255) / 256, 256>>>(a);
    }

    const dim3 blk(256);
    const int nYF = (NF + 127) / 128;   // 313
    const int nYV = (NV + 127) / 128;   // 157
    const dim3 gridF(2, nYF);
    const dim3 gridV(2, nYV);
    const dim3 gridDual(2, nYF + nYV);
    const dim3 aggBlk(32, 8);

    __half* Fcur = hFa;  __half* Vcur = hVa;
    __half* Fnxt = hFb;  __half* Vnxt = hVb;

    bool joined = false;
    for (int l = 0; l < 2; l++) {
        const __half* mWv = wm_v2f + (size_t)l * D2 * D;
        const float* mbv = mb_v2f + (size_t)l * D;
        const __half* cWv = wc_v2f + (size_t)l * D2 * D;
        const float* cbv = cb_v2f + (size_t)l * D;
        const __half* mWf = wm_f2v + (size_t)l * D2 * D;
        const float* mbf = mb_f2v + (size_t)l * D;
        const __half* cWf = wc_f2v + (size_t)l * D2 * D;
        const float* cbf = cb_f2v + (size_t)l * D;

        // ---- fork: Vh2 = Vcur@mWf2v_top + mbf (only depends on Vcur) ----
        cudaEventRecord(evLF[l], 0);
        cudaStreamWaitEvent(s2, evLF[l], 0);
        gemm_single<EP_BIAS, 256, false><<<gridV, blk, SMEM_BYTES, s2>>>(
            Vcur, nullptr, mWf, hVh2, mbf, nullptr, nullptr, NV);
        cudaEventRecord(evLJ[l], s2);

        // ---- variable -> factor ----
        gemm_dual<EP_BIAS, EP_NONE><<<gridDual, blk, SMEM_BYTES>>>(
            Fcur, mWv, hFh, mbv, NF, nYF,
            Vcur, mWv + D * D, hVh, NV);
        if (!joined) {
            cudaStreamWaitEvent(0, evJoin, 0);
            joined = true;
        }
        aggregate<<<(NF + 7) / 8, aggBlk>>>(hFh, hVh, offF, elF, hFagg, NF);
        if (l == 0)
            gemm_single<EP_RELU_BIAS, 512, false><<<gridF, blk, SMEM_BYTES>>>(
                Fcur, hFagg, cWv, Fnxt, cbv, nullptr, nullptr, NF);
        else
            gemm_single<EP_RELU_BIAS, 512, true><<<gridF, blk, SMEM_BYTES>>>(
                Fcur, hFagg, cWv, Fnxt, cbv, nullptr, outF, NF);
        { __half* t = Fcur; Fcur = Fnxt; Fnxt = t; }

        // ---- factor -> variable (Vh2 precomputed on side stream) ----
        gemm_single<EP_NONE, 256, false><<<gridF, blk, SMEM_BYTES>>>(
            Fcur, nullptr, mWf + D * D, hFh, nullptr, nullptr, nullptr, NF);
        cudaStreamWaitEvent(0, evLJ[l], 0);
        aggregate<<<(NV + 7) / 8, aggBlk>>>(hVh2, hFh, offV, elV, hVagg, NV);
        if (l == 0)
            gemm_single<EP_RELU_BIAS_RES, 512, false><<<gridV, blk, SMEM_BYTES>>>(
                Vcur, hVagg, cWf, Vnxt, cbf, Vcur, nullptr, NV);
        else
            gemm_single<EP_RELU_BIAS_RES, 512, true><<<gridV, blk, SMEM_BYTES>>>(
                Vcur, hVagg, cWf, Vnxt, cbf, Vcur, outV, NV);
        { __half* t = Vcur; Vcur = Vnxt; Vnxt = t; }
    }
    // after 2 layers: Fcur == hFa (== F2, also in outF), Vcur == hVa (in outV)

    // ---- GlobalNode attention pooling (gate forked beside the att GEMM) ----
    cudaEventRecord(evFork2, 0);
    cudaStreamWaitEvent(s2, evFork2, 0);
    gate_kernel<<<(NF + 7) / 8, 256, 0, s2>>>(Fcur, gate_W, gate_b, gate);
    cudaEventRecord(evJoin2, s2);
    gemm_single<EP_BIAS, 256, false><<<gridF, blk, SMEM_BYTES>>>(
        Fcur, nullptr, watt, hFh, att_b, nullptr, nullptr, NF);
    cudaStreamWaitEvent(0, evJoin2, 0);
    graph_agg<<<GG, 256>>>(gate, hFh, batch, gagg);
    final_g<<<GG, 256>>>(gagg, gl_W, gl_b, outG);
}

// round 17
// speedup vs baseline: 1.3628x; 1.0053x over previous
#include <cuda_runtime.h>
#include <cuda_fp16.h>
#include <math.h>
#include <stdint.h>

#define NV 20000
#define NF 40000
#define EE 320000
#define GG 64
#define D  256
#define D2 512

// ---------------- scratch (device globals; no allocation allowed) ----------
__device__ __half g_hFa[NF * D], g_hFb[NF * D], g_hFh[NF * D], g_hFagg[NF * D];
__device__ __half g_hVa[NV * D], g_hVb[NV * D], g_hVh[NV * D], g_hVagg[NV * D];
__device__ __half g_hVh2[NV * D];     // side-stream f2v top half-product
__device__ __half g_hW[1114112];
__device__ float g_gate[NF];
__device__ float g_gagg[GG * D];
__device__ int   g_part[512];
// CSR scratch
__device__ int g_cntF[NF], g_cntV[NV];
__device__ int g_offF[NF + 1], g_offV[NV + 1];
__device__ int g_curF[NF], g_curV[NV];
__device__ int g_elF[EE], g_elV[EE];

enum { EP_NONE = 0, EP_BIAS = 1, EP_RELU_BIAS = 2, EP_RELU_BIAS_RES = 3 };

__device__ __forceinline__ uint32_t smem_u32(const void* p) {
    uint32_t a;
    asm("{ .reg .u64 t; cvta.to.shared.u64 t, %1; cvt.u32.u64 %0, t; }"
        : "=r"(a) : "l"(p));
    return a;
}
__device__ __forceinline__ void ldm_x4(unsigned& r0, unsigned& r1,
                                       unsigned& r2, unsigned& r3, uint32_t a) {
    asm volatile("ldmatrix.sync.aligned.m8n8.x4.shared.b16 {%0,%1,%2,%3}, [%4];"
                 : "=r"(r0), "=r"(r1), "=r"(r2), "=r"(r3) : "r"(a));
}
__device__ __forceinline__ void ldm_x4_t(unsigned& r0, unsigned& r1,
                                         unsigned& r2, unsigned& r3, uint32_t a) {
    asm volatile("ldmatrix.sync.aligned.m8n8.x4.trans.shared.b16 {%0,%1,%2,%3}, [%4];"
                 : "=r"(r0), "=r"(r1), "=r"(r2), "=r"(r3) : "r"(a));
}
__device__ __forceinline__ void mma_f16(float* d, const unsigned* a,
                                        const unsigned* b, const float* c) {
    asm volatile(
        "mma.sync.aligned.m16n8k16.row.col.f32.f16.f16.f32 "
        "{%0,%1,%2,%3}, {%4,%5,%6,%7}, {%8,%9}, {%10,%11,%12,%13};"
        : "=f"(d[0]), "=f"(d[1]), "=f"(d[2]), "=f"(d[3])
        : "r"(a[0]), "r"(a[1]), "r"(a[2]), "r"(a[3]),
          "r"(b[0]), "r"(b[1]),
          "f"(c[0]), "f"(c[1]), "f"(c[2]), "f"(c[3]));
}

#define ASH 5120
#define BSH 4352
#define BS_BASE 40960
#define SMEM_BYTES 75776

// ---- GEMM body: C[128x128 tile] = concat-A[M x KTOT] @ W[KTOT x 256] ------
template <int MODE, int KTOT, bool F32OUT>
__device__ __forceinline__ void gemm_body(
    char* smem,
    const __half* __restrict__ A0, const __half* __restrict__ A1,
    const __half* __restrict__ W, __half* __restrict__ Cout,
    const float* __restrict__ bias, const __half* __restrict__ res,
    float* __restrict__ Cout32,
    int M, int yBlk, int xBlk)
{
    __half* AsB = reinterpret_cast<__half*>(smem);
    __half* BsB = reinterpret_cast<__half*>(smem + BS_BASE);

    const int tid  = threadIdx.x;
    const int wid  = tid >> 5;
    const int lane = tid & 31;
    const int g = lane >> 2;
    const int c = lane & 3;
    const int rowBase = yBlk * 128;
    const int colBase = xBlk * 128;
    const int wr = (wid & 1) * 64;
    const int wc = (wid >> 1) * 32;

    float acc[4][4][4];
#pragma unroll
    for (int i = 0; i < 4; i++)
#pragma unroll
        for (int j = 0; j < 4; j++)
#pragma unroll
            for (int k = 0; k < 4; k++) acc[i][j][k] = 0.f;

    auto issue = [&](int slab) {
        const __half* Asrc = (KTOT == 512 && slab >= 8) ? A1 : A0;
        const int kb = (slab * 32) & 255;
        __half* As = AsB + (slab & 3) * ASH;
        __half* Bs = BsB + (slab & 3) * BSH;
#pragma unroll
        for (int it = 0; it < 2; it++) {
            const int id = it * 256 + tid;
            const int r = id >> 2, kq = id & 3;
            const int gr = rowBase + r;
            const int grc = (gr < M) ? gr : (M - 1);
            const __half* src = &Asrc[(size_t)grc * D + kb + kq * 8];
            const uint32_t dst = smem_u32(As + r * 40 + kq * 8);
            const int sz = (gr < M) ? 16 : 0;
            asm volatile("cp.async.cg.shared.global [%0], [%1], 16, %2;\n"
                         :: "r"(dst), "l"(src), "r"(sz) : "memory");
        }
#pragma unroll
        for (int it = 0; it < 2; it++) {
            const int id = it * 256 + tid;
            const int kk = id >> 4, n8 = (id & 15) * 8;
            const __half* src = &W[(size_t)(slab * 32 + kk) * D + colBase + n8];
            const uint32_t dst = smem_u32(Bs + kk * 136 + n8);
            asm volatile("cp.async.cg.shared.global [%0], [%1], 16;\n"
                         :: "r"(dst), "l"(src) : "memory");
        }
        asm volatile("cp.async.commit_group;\n" ::: "memory");
    };

    constexpr int NSLAB = KTOT / 32;
    issue(0); issue(1); issue(2);

    for (int s = 0; s < NSLAB; s++) {
        asm volatile("cp.async.wait_group 2;\n" ::: "memory");
        __syncthreads();
        if (s + 3 < NSLAB) issue(s + 3);

        const uint32_t aBase = smem_u32(AsB + (s & 3) * ASH);
        const uint32_t bBase = smem_u32(BsB + (s & 3) * BSH);
#pragma unroll
        for (int ks = 0; ks < 32; ks += 16) {
            unsigned a[4][4], b[4][2];
#pragma unroll
            for (int mf = 0; mf < 4; mf++) {
                const uint32_t addr = aBase +
                    (((wr + mf * 16 + (lane & 15)) * 40 + ks + (lane >> 4) * 8) << 1);
                ldm_x4(a[mf][0], a[mf][1], a[mf][2], a[mf][3], addr);
            }
#pragma unroll
            for (int p = 0; p < 2; p++) {
                const uint32_t addr = bBase +
                    ((((ks + (lane & 7) + ((lane >> 3) & 1) * 8)) * 136 +
                      wc + p * 16 + (lane >> 4) * 8) << 1);
                ldm_x4_t(b[2 * p][0], b[2 * p][1], b[2 * p + 1][0], b[2 * p + 1][1], addr);
            }
#pragma unroll
            for (int mf = 0; mf < 4; mf++)
#pragma unroll
                for (int nf = 0; nf < 4; nf++)
                    mma_f16(acc[mf][nf], a[mf], b[nf], acc[mf][nf]);
        }
    }

#pragma unroll
    for (int mf = 0; mf < 4; mf++) {
#pragma unroll
        for (int half = 0; half < 2; half++) {
            const int r = rowBase + wr + mf * 16 + g + half * 8;
            if (r >= M) continue;
#pragma unroll
            for (int nf = 0; nf < 4; nf++) {
                const int col = colBase + wc + nf * 8 + 2 * c;
                float2 v = make_float2(acc[mf][nf][half * 2], acc[mf][nf][half * 2 + 1]);
                if (MODE == EP_BIAS) {
                    v.x += bias[col + 0];
                    v.y += bias[col + 1];
                } else if (MODE == EP_RELU_BIAS || MODE == EP_RELU_BIAS_RES) {
                    v.x = fmaxf(v.x + bias[col + 0], 0.f);
                    v.y = fmaxf(v.y + bias[col + 1], 0.f);
                    if (MODE == EP_RELU_BIAS_RES) {
                        const __half2 rr = *reinterpret_cast<const __half2*>(&res[(size_t)r * D + col]);
                        const float2 rf = __half22float2(rr);
                        v.x += rf.x; v.y += rf.y;
                    }
                }
                *reinterpret_cast<__half2*>(&Cout[(size_t)r * D + col]) =
                    __floats2half2_rn(v.x, v.y);
                if (F32OUT) {
                    const float2 hf = __half22float2(__floats2half2_rn(v.x, v.y));
                    *reinterpret_cast<float2*>(&Cout32[(size_t)r * D + col]) = hf;
                }
            }
        }
    }
}

template <int MODE, int KTOT, bool F32OUT>
__global__ __launch_bounds__(256, 2)
void gemm_single(const __half* __restrict__ A0, const __half* __restrict__ A1,
                 const __half* __restrict__ W, __half* __restrict__ Cout,
                 const float* __restrict__ bias, const __half* __restrict__ res,
                 float* __restrict__ Cout32, int M)
{
    extern __shared__ char smem[];
    gemm_body<MODE, KTOT, F32OUT>(smem, A0, A1, W, Cout, bias, res, Cout32, M,
                                  blockIdx.y, blockIdx.x);
}

template <int MODEA, int MODEB>
__global__ __launch_bounds__(256, 2)
void gemm_dual(const __half* __restrict__ Aa, const __half* __restrict__ Wa,
               __half* __restrict__ Ca, const float* __restrict__ biasa,
               int Ma, int nYa,
               const __half* __restrict__ Ab, const __half* __restrict__ Wb,
               __half* __restrict__ Cb, int Mb)
{
    extern __shared__ char smem[];
    if ((int)blockIdx.y < nYa)
        gemm_body<MODEA, 256, false>(smem, Aa, nullptr, Wa, Ca, biasa, nullptr,
                                     nullptr, Ma, blockIdx.y, blockIdx.x);
    else
        gemm_body<MODEB, 256, false>(smem, Ab, nullptr, Wb, Cb, nullptr, nullptr,
                                     nullptr, Mb, blockIdx.y - nYa, blockIdx.x);
}

// ---------------- batched fp32 -> fp16 convert -------------------------------
struct CvtArgs {
    const float* src[7];
    __half* dst[7];
    int off[8];
};
__global__ __launch_bounds__(256)
void convert_multi(CvtArgs a)
{
    const int i = blockIdx.x * 256 + threadIdx.x;
    if (i >= a.off[7]) return;
    int s = 0;
    while (i >= a.off[s + 1]) s++;
    const int j = i - a.off[s];
    a.dst[s][j] = __float2half_rn(__ldg(&a.src[s][j]));
}

// ---------------- CSR build --------------------------------------------------
__global__ __launch_bounds__(256)
void hist_kernel(const int* __restrict__ src, const int* __restrict__ dst,
                 int* cntF, int* cntV)
{
    const int e = blockIdx.x * 256 + threadIdx.x;
    if (e >= EE) return;
    atomicAdd(&cntF[__ldg(&dst[e])], 1);
    atomicAdd(&cntV[__ldg(&src[e])], 1);
}

__global__ __launch_bounds__(256)
void blk_sum2(const int* __restrict__ cntF, int nF, const int* __restrict__ cntV,
              int nV, int nbF, int* __restrict__ part)
{
    const bool isV = (int)blockIdx.x >= nbF;
    const int b = isV ? (blockIdx.x - nbF) : blockIdx.x;
    const int* cnt = isV ? cntV : cntF;
    const int n = isV ? nV : nF;
    const int i = b * 256 + threadIdx.x;
    int x = (i < n) ? cnt[i] : 0;
#pragma unroll
    for (int o = 16; o > 0; o >>= 1) x += __shfl_xor_sync(0xffffffffu, x, o);
    __shared__ int ws[8];
    if ((threadIdx.x & 31) == 0) ws[threadIdx.x >> 5] = x;
    __syncthreads();
    if (threadIdx.x == 0) {
        int t = 0;
#pragma unroll
        for (int q = 0; q < 8; q++) t += ws[q];
        part[(isV ? 256 : 0) + b] = t;
    }
}

__global__ __launch_bounds__(256)
void scan_part2(int* __restrict__ part, int nbF, int nbV,
                int* __restrict__ totF, int* __restrict__ totV)
{
    const bool isV = blockIdx.x == 1;
    int* p = part + (isV ? 256 : 0);
    const int nb = isV ? nbV : nbF;
    int* total_out = isV ? totV : totF;
    const int t = threadIdx.x, lane = t & 31, w = t >> 5;
    const int x = (t < nb) ? p[t] : 0;
    int incl = x;
#pragma unroll
    for (int o = 1; o < 32; o <<= 1) {
        const int v = __shfl_up_sync(0xffffffffu, incl, o);
        if (lane >= o) incl += v;
    }
    __shared__ int ws[8], wex[8];
    if (lane == 31) ws[w] = incl;
    __syncthreads();
    if (t == 0) {
        int s = 0;
#pragma unroll
        for (int q = 0; q < 8; q++) { wex[q] = s; s += ws[q]; }
        total_out[0] = s;
    }
    __syncthreads();
    if (t < nb) p[t] = wex[w] + incl - x;
}

__global__ __launch_bounds__(256)
void scan_apply2(const int* __restrict__ cntF, int nF,
                 const int* __restrict__ cntV, int nV, int nbF,
                 const int* __restrict__ part,
                 int* __restrict__ offF, int* __restrict__ curF,
                 int* __restrict__ offV, int* __restrict__ curV)
{
    const bool isV = (int)blockIdx.x >= nbF;
    const int b = isV ? (blockIdx.x - nbF) : blockIdx.x;
    const int* cnt = isV ? cntV : cntF;
    const int n = isV ? nV : nF;
    int* off = isV ? offV : offF;
    int* cur = isV ? curV : curF;
    const int base = isV ? 256 : 0;
    const int i = b * 256 + threadIdx.x;
    const int t = threadIdx.x, lane = t & 31, w = t >> 5;
    const int x = (i < n) ? cnt[i] : 0;
    int incl = x;
#pragma unroll
    for (int o = 1; o < 32; o <<= 1) {
        const int v = __shfl_up_sync(0xffffffffu, incl, o);
        if (lane >= o) incl += v;
    }
    __shared__ int ws[8], wex[8];
    if (lane == 31) ws[w] = incl;
    __syncthreads();
    if (t == 0) {
        int s = 0;
#pragma unroll
        for (int q = 0; q < 8; q++) { wex[q] = s; s += ws[q]; }
    }
    __syncthreads();
    const int ex = part[base + b] + wex[w] + incl - x;
    if (i < n) { off[i] = ex; cur[i] = ex; }
}

__global__ __launch_bounds__(256)
void scatter_kernel(const int* __restrict__ src, const int* __restrict__ dst,
                    int* curF, int* curV, int* elF, int* elV)
{
    const int e = blockIdx.x * 256 + threadIdx.x;
    if (e >= EE) return;
    const int s = __ldg(&src[e]);
    const int d2 = __ldg(&dst[e]);
    elF[atomicAdd(&curF[d2], 1)] = s;
    elV[atomicAdd(&curV[s], 1)] = d2;
}

// ---------------- CSR gather-aggregate (half in, half out) -------------------
// edge loop unrolled x2: two independent row gathers in flight (MLP).
__global__ __launch_bounds__(256)
void aggregate(const __half* __restrict__ Hself, const __half* __restrict__ Hother,
               const int* __restrict__ off, const int* __restrict__ elist,
               __half* __restrict__ out, int n)
{
    const int row = blockIdx.x * 8 + threadIdx.y;
    if (row >= n) return;
    const int d = threadIdx.x * 8;
    const __half2* sp = reinterpret_cast<const __half2*>(&Hself[(size_t)row * D + d]);
    float2 s0 = __half22float2(sp[0]), s1 = __half22float2(sp[1]);
    float2 s2 = __half22float2(sp[2]), s3 = __half22float2(sp[3]);
    float a0x = 0.f, a0y = 0.f, a1x = 0.f, a1y = 0.f;
    float a2x = 0.f, a2y = 0.f, a3x = 0.f, a3y = 0.f;
    int j = __ldg(&off[row]);
    const int e = __ldg(&off[row + 1]);
    for (; j + 2 <= e; j += 2) {
        const int o0 = __ldg(&elist[j]);
        const int o1 = __ldg(&elist[j + 1]);
        const __half2* p0 = reinterpret_cast<const __half2*>(&Hother[(size_t)o0 * D + d]);
        const __half2* p1 = reinterpret_cast<const __half2*>(&Hother[(size_t)o1 * D + d]);
        const float2 u0 = __half22float2(p0[0]), u1 = __half22float2(p0[1]);
        const float2 u2 = __half22float2(p0[2]), u3 = __half22float2(p0[3]);
        const float2 w0 = __half22float2(p1[0]), w1 = __half22float2(p1[1]);
        const float2 w2 = __half22float2(p1[2]), w3 = __half22float2(p1[3]);
        a0x += fmaxf(s0.x + u0.x, 0.f); a0y += fmaxf(s0.y + u0.y, 0.f);
        a1x += fmaxf(s1.x + u1.x, 0.f); a1y += fmaxf(s1.y + u1.y, 0.f);
        a2x += fmaxf(s2.x + u2.x, 0.f); a2y += fmaxf(s2.y + u2.y, 0.f);
        a3x += fmaxf(s3.x + u3.x, 0.f); a3y += fmaxf(s3.y + u3.y, 0.f);
        a0x += fmaxf(s0.x + w0.x, 0.f); a0y += fmaxf(s0.y + w0.y, 0.f);
        a1x += fmaxf(s1.x + w1.x, 0.f); a1y += fmaxf(s1.y + w1.y, 0.f);
        a2x += fmaxf(s2.x + w2.x, 0.f); a2y += fmaxf(s2.y + w2.y, 0.f);
        a3x += fmaxf(s3.x + w3.x, 0.f); a3y += fmaxf(s3.y + w3.y, 0.f);
    }
    if (j < e) {
        const int o0 = __ldg(&elist[j]);
        const __half2* p0 = reinterpret_cast<const __half2*>(&Hother[(size_t)o0 * D + d]);
        const float2 u0 = __half22float2(p0[0]), u1 = __half22float2(p0[1]);
        const float2 u2 = __half22float2(p0[2]), u3 = __half22float2(p0[3]);
        a0x += fmaxf(s0.x + u0.x, 0.f); a0y += fmaxf(s0.y + u0.y, 0.f);
        a1x += fmaxf(s1.x + u1.x, 0.f); a1y += fmaxf(s1.y + u1.y, 0.f);
        a2x += fmaxf(s2.x + u2.x, 0.f); a2y += fmaxf(s2.y + u2.y, 0.f);
        a3x += fmaxf(s3.x + u3.x, 0.f); a3y += fmaxf(s3.y + u3.y, 0.f);
    }
    __half2* op2 = reinterpret_cast<__half2*>(&out[(size_t)row * D + d]);
    op2[0] = __floats2half2_rn(a0x, a0y);
    op2[1] = __floats2half2_rn(a1x, a1y);
    op2[2] = __floats2half2_rn(a2x, a2y);
    op2[3] = __floats2half2_rn(a3x, a3y);
}

// ---------------- attention pooling -----------------------------------------
__global__ __launch_bounds__(256)
void gate_kernel(const __half* __restrict__ F, const float* __restrict__ gW,
                 const float* __restrict__ gb, float* __restrict__ gate)
{
    const int w = threadIdx.x >> 5, lane = threadIdx.x & 31;
    const int row = blockIdx.x * 8 + w;
    if (row >= NF) return;
    float s = 0.f;
#pragma unroll
    for (int i = 0; i < 8; i++) {
        const int k = lane + i * 32;
        s += __half2float(F[(size_t)row * D + k]) * __ldg(&gW[k]);
    }
#pragma unroll
    for (int o = 16; o > 0; o >>= 1) s += __shfl_xor_sync(0xffffffff, s, o);
    if (lane == 0) gate[row] = s + gb[0];
}

__device__ __forceinline__ int lbound(const int* __restrict__ a, int n, int v)
{
    int lo = 0, hi = n;
    while (lo < hi) {
        const int mid = (lo + hi) >> 1;
        if (a[mid] < v) lo = mid + 1; else hi = mid;
    }
    return lo;
}

__global__ __launch_bounds__(256)
void graph_agg(const float* __restrict__ gate, const __half* __restrict__ T,
               const int* __restrict__ batch, float* __restrict__ gagg)
{
    __shared__ float red[256];
    __shared__ int sse[2];
    const int g = blockIdx.x, tid = threadIdx.x;
    if (tid == 0) sse[0] = lbound(batch, NF, g);
    if (tid == 1) sse[1] = lbound(batch, NF, g + 1);
    __syncthreads();
    const int s = sse[0], e = sse[1];

    float m = -INFINITY;
    for (int i = s + tid; i < e; i += 256) m = fmaxf(m, __ldg(&gate[i]));
    red[tid] = m; __syncthreads();
    for (int o = 128; o > 0; o >>= 1) {
        if (tid < o) red[tid] = fmaxf(red[tid], red[tid + o]);
        __syncthreads();
    }
    const float mm = red[0]; __syncthreads();

    float sum = 0.f;
    for (int i = s + tid; i < e; i += 256) sum += expf(__ldg(&gate[i]) - mm);
    red[tid] = sum; __syncthreads();
    for (int o = 128; o > 0; o >>= 1) {
        if (tid < o) red[tid] += red[tid + o];
        __syncthreads();
    }
    const float inv = (e > s) ? 1.f / red[0] : 0.f;

    float acc = 0.f;
    for (int i = s; i < e; i++) {
        const float alpha = expf(__ldg(&gate[i]) - mm) * inv;
        acc += alpha * __half2float(T[(size_t)i * D + tid]);
    }
    gagg[g * D + tid] = acc;
}

__global__ __launch_bounds__(256)
void final_g(const float* __restrict__ gagg, const float* __restrict__ glW,
             const float* __restrict__ glb, float* __restrict__ out)
{
    __shared__ float row[D];
    const int g = blockIdx.x, c = threadIdx.x;
    row[c] = gagg[g * D + c];
    __syncthreads();
    float s = glb[c];
#pragma unroll 8
    for (int k = 0; k < D; k++) s += row[k] * glW[(size_t)k * D + c];
    out[(size_t)g * D + c] = fmaxf(s, 0.f);
}

// ---------------------------------------------------------------------------
extern "C" void kernel_launch(void* const* d_in, const int* in_sizes, int n_in,
                              void* d_out, int out_size)
{
    const float* variables = (const float*)d_in[0];
    const float* factors   = (const float*)d_in[1];
    // d_in[2] = edge_attr (unused by the math)
    const int* edge_index  = (const int*)d_in[3];
    const int* batch       = (const int*)d_in[4];
    const float* mW_v2f = (const float*)d_in[5];
    const float* mb_v2f = (const float*)d_in[6];
    const float* cW_v2f = (const float*)d_in[7];
    const float* cb_v2f = (const float*)d_in[8];
    const float* mW_f2v = (const float*)d_in[9];
    const float* mb_f2v = (const float*)d_in[10];
    const float* cW_f2v = (const float*)d_in[11];
    const float* cb_f2v = (const float*)d_in[12];
    const float* gate_W = (const float*)d_in[13];
    const float* gate_b = (const float*)d_in[14];
    const float* att_W  = (const float*)d_in[15];
    const float* att_b  = (const float*)d_in[16];
    const float* gl_W   = (const float*)d_in[17];
    const float* gl_b   = (const float*)d_in[18];

    const int* src = edge_index;        // row 0: variable idx
    const int* dst = edge_index + EE;   // row 1: factor idx

    float* outV = (float*)d_out;
    float* outF = outV + (size_t)NV * D;
    float* outG = outF + (size_t)NF * D;

    __half *hFa, *hFb, *hFh, *hFagg, *hVa, *hVb, *hVh, *hVagg, *hVh2, *hW;
    float *gate, *gagg;
    int *cntF, *cntV, *offF, *offV, *curF, *curV, *elF, *elV, *part;
    cudaGetSymbolAddress((void**)&hFa, g_hFa);
    cudaGetSymbolAddress((void**)&hFb, g_hFb);
    cudaGetSymbolAddress((void**)&hFh, g_hFh);
    cudaGetSymbolAddress((void**)&hFagg, g_hFagg);
    cudaGetSymbolAddress((void**)&hVa, g_hVa);
    cudaGetSymbolAddress((void**)&hVb, g_hVb);
    cudaGetSymbolAddress((void**)&hVh, g_hVh);
    cudaGetSymbolAddress((void**)&hVagg, g_hVagg);
    cudaGetSymbolAddress((void**)&hVh2, g_hVh2);
    cudaGetSymbolAddress((void**)&hW,  g_hW);
    cudaGetSymbolAddress((void**)&gate, g_gate);
    cudaGetSymbolAddress((void**)&gagg, g_gagg);
    cudaGetSymbolAddress((void**)&part, g_part);
    cudaGetSymbolAddress((void**)&cntF, g_cntF);
    cudaGetSymbolAddress((void**)&cntV, g_cntV);
    cudaGetSymbolAddress((void**)&offF, g_offF);
    cudaGetSymbolAddress((void**)&offV, g_offV);
    cudaGetSymbolAddress((void**)&curF, g_curF);
    cudaGetSymbolAddress((void**)&curV, g_curV);
    cudaGetSymbolAddress((void**)&elF,  g_elF);
    cudaGetSymbolAddress((void**)&elV,  g_elV);

    __half* wm_v2f = hW;
    __half* wc_v2f = hW + 262144;
    __half* wm_f2v = hW + 524288;
    __half* wc_f2v = hW + 786432;
    __half* watt   = hW + 1048576;

    cudaFuncSetAttribute(gemm_single<EP_BIAS, 256, false>,           cudaFuncAttributeMaxDynamicSharedMemorySize, SMEM_BYTES);
    cudaFuncSetAttribute(gemm_single<EP_NONE, 256, false>,           cudaFuncAttributeMaxDynamicSharedMemorySize, SMEM_BYTES);
    cudaFuncSetAttribute(gemm_single<EP_RELU_BIAS, 512, false>,      cudaFuncAttributeMaxDynamicSharedMemorySize, SMEM_BYTES);
    cudaFuncSetAttribute(gemm_single<EP_RELU_BIAS, 512, true>,       cudaFuncAttributeMaxDynamicSharedMemorySize, SMEM_BYTES);
    cudaFuncSetAttribute(gemm_single<EP_RELU_BIAS_RES, 512, false>,  cudaFuncAttributeMaxDynamicSharedMemorySize, SMEM_BYTES);
    cudaFuncSetAttribute(gemm_single<EP_RELU_BIAS_RES, 512, true>,   cudaFuncAttributeMaxDynamicSharedMemorySize, SMEM_BYTES);
    cudaFuncSetAttribute(gemm_dual<EP_BIAS, EP_NONE>,                cudaFuncAttributeMaxDynamicSharedMemorySize, SMEM_BYTES);

    // side stream + events (host-side objects only; created once, reused)
    static cudaStream_t s2 = nullptr;
    static cudaEvent_t evFork = nullptr, evJoin = nullptr;
    static cudaEvent_t evFork2 = nullptr, evJoin2 = nullptr;
    static cudaEvent_t evLF[2] = {nullptr, nullptr};
    static cudaEvent_t evLJ[2] = {nullptr, nullptr};
    if (s2 == nullptr) {
        cudaStreamCreateWithFlags(&s2, cudaStreamNonBlocking);
        cudaEventCreateWithFlags(&evFork,  cudaEventDisableTiming);
        cudaEventCreateWithFlags(&evJoin,  cudaEventDisableTiming);
        cudaEventCreateWithFlags(&evFork2, cudaEventDisableTiming);
        cudaEventCreateWithFlags(&evJoin2, cudaEventDisableTiming);
        for (int i = 0; i < 2; i++) {
            cudaEventCreateWithFlags(&evLF[i], cudaEventDisableTiming);
            cudaEventCreateWithFlags(&evLJ[i], cudaEventDisableTiming);
        }
    }

    // ---- fork: CSR build chain on side stream ----
    cudaEventRecord(evFork, 0);
    cudaStreamWaitEvent(s2, evFork, 0);
    cudaMemsetAsync(cntF, 0, NF * sizeof(int), s2);
    cudaMemsetAsync(cntV, 0, NV * sizeof(int), s2);
    const int eb = (EE + 255) / 256;
    hist_kernel<<<eb, 256, 0, s2>>>(src, dst, cntF, cntV);
    const int nbF = (NF + 255) / 256, nbV = (NV + 255) / 256;
    blk_sum2<<<nbF + nbV, 256, 0, s2>>>(cntF, NF, cntV, NV, nbF, part);
    scan_part2<<<2, 256, 0, s2>>>(part, nbF, nbV, offF + NF, offV + NV);
    scan_apply2<<<nbF + nbV, 256, 0, s2>>>(cntF, NF, cntV, NV, nbF, part,
                                           offF, curF, offV, curV);
    scatter_kernel<<<eb, 256, 0, s2>>>(src, dst, curF, curV, elF, elV);
    cudaEventRecord(evJoin, s2);

    // ---- main stream: convert inputs + weights to half ----
    {
        CvtArgs a;
        a.src[0] = variables; a.dst[0] = hVa;
        a.src[1] = factors;   a.dst[1] = hFa;
        a.src[2] = mW_v2f;    a.dst[2] = wm_v2f;
        a.src[3] = cW_v2f;    a.dst[3] = wc_v2f;
        a.src[4] = mW_f2v;    a.dst[4] = wm_f2v;
        a.src[5] = cW_f2v;    a.dst[5] = wc_f2v;
        a.src[6] = att_W;     a.dst[6] = watt;
        const int sz[7] = {NV * D, NF * D, 262144, 262144, 262144, 262144, 65536};
        a.off[0] = 0;
        for (int i = 0; i < 7; i++) a.off[i + 1] = a.off[i] + sz[i];
        convert_multi<<<(a.off[7] + 255) / 256, 256>>>(a);
    }

    const dim3 blk(256);
    const int nYF = (NF + 127) / 128;   // 313
    const int nYV = (NV + 127) / 128;   // 157
    const dim3 gridF(2, nYF);
    const dim3 gridV(2, nYV);
    const dim3 gridDual(2, nYF + nYV);
    const dim3 aggBlk(32, 8);

    __half* Fcur = hFa;  __half* Vcur = hVa;
    __half* Fnxt = hFb;  __half* Vnxt = hVb;

    bool joined = false;
    for (int l = 0; l < 2; l++) {
        const __half* mWv = wm_v2f + (size_t)l * D2 * D;
        const float* mbv = mb_v2f + (size_t)l * D;
        const __half* cWv = wc_v2f + (size_t)l * D2 * D;
        const float* cbv = cb_v2f + (size_t)l * D;
        const __half* mWf = wm_f2v + (size_t)l * D2 * D;
        const float* mbf = mb_f2v + (size_t)l * D;
        const __half* cWf = wc_f2v + (size_t)l * D2 * D;
        const float* cbf = cb_f2v + (size_t)l * D;

        // ---- fork: Vh2 = Vcur@mWf2v_top + mbf (only depends on Vcur) ----
        cudaEventRecord(evLF[l], 0);
        cudaStreamWaitEvent(s2, evLF[l], 0);
        gemm_single<EP_BIAS, 256, false><<<gridV, blk, SMEM_BYTES, s2>>>(
            Vcur, nullptr, mWf, hVh2, mbf, nullptr, nullptr, NV);
        cudaEventRecord(evLJ[l], s2);

        // ---- variable -> factor ----
        gemm_dual<EP_BIAS, EP_NONE><<<gridDual, blk, SMEM_BYTES>>>(
            Fcur, mWv, hFh, mbv, NF, nYF,
            Vcur, mWv + D * D, hVh, NV);
        if (!joined) {
            cudaStreamWaitEvent(0, evJoin, 0);
            joined = true;
        }
        aggregate<<<(NF + 7) / 8, aggBlk>>>(hFh, hVh, offF, elF, hFagg, NF);
        if (l == 0)
            gemm_single<EP_RELU_BIAS, 512, false><<<gridF, blk, SMEM_BYTES>>>(
                Fcur, hFagg, cWv, Fnxt, cbv, nullptr, nullptr, NF);
        else
            gemm_single<EP_RELU_BIAS, 512, true><<<gridF, blk, SMEM_BYTES>>>(
                Fcur, hFagg, cWv, Fnxt, cbv, nullptr, outF, NF);
        { __half* t = Fcur; Fcur = Fnxt; Fnxt = t; }

        // ---- factor -> variable (Vh2 precomputed on side stream) ----
        gemm_single<EP_NONE, 256, false><<<gridF, blk, SMEM_BYTES>>>(
            Fcur, nullptr, mWf + D * D, hFh, nullptr, nullptr, nullptr, NF);
        cudaStreamWaitEvent(0, evLJ[l], 0);
        aggregate<<<(NV + 7) / 8, aggBlk>>>(hVh2, hFh, offV, elV, hVagg, NV);
        if (l == 0)
            gemm_single<EP_RELU_BIAS_RES, 512, false><<<gridV, blk, SMEM_BYTES>>>(
                Vcur, hVagg, cWf, Vnxt, cbf, Vcur, nullptr, NV);
        else
            gemm_single<EP_RELU_BIAS_RES, 512, true><<<gridV, blk, SMEM_BYTES>>>(
                Vcur, hVagg, cWf, Vnxt, cbf, Vcur, outV, NV);
        { __half* t = Vcur; Vcur = Vnxt; Vnxt = t; }
    }
    // after 2 layers: Fcur == hFa (== F2, also in outF), Vcur == hVa (in outV)

    // ---- GlobalNode attention pooling (gate forked beside the att GEMM) ----
    cudaEventRecord(evFork2, 0);
    cudaStreamWaitEvent(s2, evFork2, 0);
    gate_kernel<<<(NF + 7) / 8, 256, 0, s2>>>(Fcur, gate_W, gate_b, gate);
    cudaEventRecord(evJoin2, s2);
    gemm_single<EP_BIAS, 256, false><<<gridF, blk, SMEM_BYTES>>>(
        Fcur, nullptr, watt, hFh, att_b, nullptr, nullptr, NF);
    cudaStreamWaitEvent(0, evJoin2, 0);
    graph_agg<<<GG, 256>>>(gate, hFh, batch, gagg);
    final_g<<<GG, 256>>>(gagg, gl_W, gl_b, outG);
}